// round 3
// baseline (speedup 1.0000x reference)
#include <cuda_runtime.h>
#include <math.h>

#define BB 2
#define HH 16
#define NN 2048
#define DD 64
#define BH (BB*HH)
#define SCALE 0.03125f   // 1/(sqrt(16)*sqrt(64))

// ---------------- scratch (static device globals; no allocation) ----------------
__device__ float g_qt[(size_t)BH*DD*NN];       // q transposed [b,h,d,n]
__device__ float g_kt[(size_t)BH*DD*NN];
__device__ float g_qm[(size_t)BH*DD*NN];       // head-mixed q [b,h,d,n]
__device__ float g_km[(size_t)BH*DD*NN];
__device__ float g_S [(size_t)BH*NN*NN];       // scores -> exp(s-m) in place (512MB)
__device__ float g_PT[(size_t)BH*NN*NN];       // mixed probs, TRANSPOSED [b,e,j,i] (512MB)
__device__ float g_rsum[(size_t)BH*NN];        // softmax row sums

// ---------------- K1a: [b,h,n,d] -> [b,h,d,n] transpose ----------------
__global__ void k_transpose(const float* __restrict__ src, int which)
{
    __shared__ float t[32][33];
    float* dst = which ? g_kt : g_qt;
    int n0 = blockIdx.x * 32;
    int d0 = blockIdx.y * 32;
    int bf = blockIdx.z;
    const float* s = src + (size_t)bf * NN * DD;
    float*       o = dst + (size_t)bf * DD * NN;
    int x = threadIdx.x, y = threadIdx.y;   // 32 x 8
#pragma unroll
    for (int p = 0; p < 4; p++) {
        int r = y + p * 8;
        t[r][x] = s[(size_t)(n0 + r) * DD + d0 + x];
    }
    __syncthreads();
#pragma unroll
    for (int p = 0; p < 4; p++) {
        int r = y + p * 8;
        o[(size_t)(d0 + r) * NN + n0 + x] = t[x][r];
    }
}

// ---------------- K1b: head-mix q,k with W_pre ----------------
__global__ void k_mix(const float* __restrict__ Wpre)
{
    __shared__ float Ws[HH][HH];
    int tid = threadIdx.x;
    if (tid < HH * HH) Ws[tid >> 4][tid & 15] = Wpre[tid];
    __syncthreads();

    size_t idx = (size_t)blockIdx.x * blockDim.x + tid;   // over B*D*N = 262144
    int n = (int)(idx % NN);
    int d = (int)((idx / NN) % DD);
    int b = (int)(idx / ((size_t)NN * DD));

    float xv[HH];
#pragma unroll
    for (int f = 0; f < HH; f++)
        xv[f] = g_qt[((size_t)(b * HH + f) * DD + d) * NN + n];
#pragma unroll
    for (int e = 0; e < HH; e++) {
        float a = 0.f;
#pragma unroll
        for (int f = 0; f < HH; f++) a += Ws[e][f] * xv[f];
        g_qm[((size_t)(b * HH + e) * DD + d) * NN + n] = a;
    }
#pragma unroll
    for (int f = 0; f < HH; f++)
        xv[f] = g_kt[((size_t)(b * HH + f) * DD + d) * NN + n];
#pragma unroll
    for (int e = 0; e < HH; e++) {
        float a = 0.f;
#pragma unroll
        for (int f = 0; f < HH; f++) a += Ws[e][f] * xv[f];
        g_km[((size_t)(b * HH + e) * DD + d) * NN + n] = a;
    }
}

// ---------------- K2: lower-tri 128x128x64 SGEMM, raw scaled scores ----------------
__global__ void __launch_bounds__(256) k_qk()
{
    extern __shared__ float sm[];
    float* Qs = sm;              // [64][128]
    float* Ks = sm + 64 * 128;   // [64][128]

    int pidx = blockIdx.x;       // 0..135 lower-tri pair (ti>=tj), 16 tiles/dim
    int ti = (int)((sqrtf(8.f * pidx + 1.f) - 1.f) * 0.5f);
    while ((ti + 1) * (ti + 2) / 2 <= pidx) ti++;
    while (ti * (ti + 1) / 2 > pidx) ti--;
    int tj = pidx - ti * (ti + 1) / 2;
    int bh = blockIdx.y;

    const float* qb = g_qm + (size_t)bh * DD * NN + ti * 128;  // [d][n] layout
    const float* kb = g_km + (size_t)bh * DD * NN + tj * 128;

    int tid = threadIdx.x;
    int c4 = tid & 31, rr = tid >> 5;
#pragma unroll
    for (int p = 0; p < 8; p++) {
        int d = p * 8 + rr;
        *(float4*)&Qs[d * 128 + c4 * 4] = *(const float4*)&qb[(size_t)d * NN + c4 * 4];
        *(float4*)&Ks[d * 128 + c4 * 4] = *(const float4*)&kb[(size_t)d * NN + c4 * 4];
    }
    __syncthreads();

    int ty = tid >> 4, tx = tid & 15;
    int m0 = ty * 8, n0 = tx * 8;
    float acc[8][8];
#pragma unroll
    for (int r = 0; r < 8; r++)
#pragma unroll
        for (int u = 0; u < 8; u++) acc[r][u] = 0.f;

#pragma unroll 4
    for (int d = 0; d < 64; d++) {
        float4 a0 = *(float4*)&Qs[d * 128 + m0];
        float4 a1 = *(float4*)&Qs[d * 128 + m0 + 4];
        float4 b0 = *(float4*)&Ks[d * 128 + n0];
        float4 b1 = *(float4*)&Ks[d * 128 + n0 + 4];
        float a[8] = {a0.x, a0.y, a0.z, a0.w, a1.x, a1.y, a1.z, a1.w};
        float b[8] = {b0.x, b0.y, b0.z, b0.w, b1.x, b1.y, b1.z, b1.w};
#pragma unroll
        for (int r = 0; r < 8; r++)
#pragma unroll
            for (int u = 0; u < 8; u++)
                acc[r][u] += a[r] * b[u];
    }

    float* outp = g_S + (size_t)bh * NN * NN + (size_t)(ti * 128) * NN + tj * 128;
#pragma unroll
    for (int r = 0; r < 8; r++) {
        float4 o0 = make_float4(acc[r][0] * SCALE, acc[r][1] * SCALE, acc[r][2] * SCALE, acc[r][3] * SCALE);
        float4 o1 = make_float4(acc[r][4] * SCALE, acc[r][5] * SCALE, acc[r][6] * SCALE, acc[r][7] * SCALE);
        *(float4*)&outp[(size_t)(m0 + r) * NN + n0]     = o0;
        *(float4*)&outp[(size_t)(m0 + r) * NN + n0 + 4] = o1;
    }
}

// ---------------- K3: per-row softmax (in place: S -> exp(S-m)), row sums ----------------
__global__ void k_softmax()
{
    int i  = blockIdx.x;
    int bh = blockIdx.y;
    float* row = g_S + (size_t)bh * NN * NN + (size_t)i * NN;
    int len = i + 1;
    int tid = threadIdx.x;     // 128
    __shared__ float red[128];

    float m = -3.4e38f;
    for (int j = tid; j < len; j += 128) m = fmaxf(m, row[j]);
    red[tid] = m;
    __syncthreads();
    for (int s = 64; s > 0; s >>= 1) {
        if (tid < s) red[tid] = fmaxf(red[tid], red[tid + s]);
        __syncthreads();
    }
    m = red[0];
    __syncthreads();

    float sum = 0.f;
    for (int j = tid; j < len; j += 128) {
        float e = expf(row[j] - m);
        row[j] = e;
        sum += e;
    }
    int jmax = ((i >> 5) + 1) << 5;          // zero-pad to 32 boundary for the mix kernel
    for (int j = len + tid; j < jmax; j += 128) row[j] = 0.f;

    red[tid] = sum;
    __syncthreads();
    for (int s = 64; s > 0; s >>= 1) {
        if (tid < s) red[tid] += red[tid + s];
        __syncthreads();
    }
    if (tid == 0) g_rsum[(size_t)bh * NN + i] = red[0];
}

// ---------------- K4: normalize + 16x16 head-mix of probs, write transposed P^T ----------------
__global__ void __launch_bounds__(256) k_mixp(const float* __restrict__ Wpost)
{
    extern __shared__ float Es[];        // [16][32][33]
    __shared__ float Ws[HH][HH];
    __shared__ float invl[HH][32];

    int pidx = blockIdx.x;               // 0..2079 lower-tri pair over 64 tiles
    int b = blockIdx.y;
    int ti = (int)((sqrtf(8.f * pidx + 1.f) - 1.f) * 0.5f);
    while ((ti + 1) * (ti + 2) / 2 <= pidx) ti++;
    while (ti * (ti + 1) / 2 > pidx) ti--;
    int tj = pidx - ti * (ti + 1) / 2;
    int i0 = ti * 32, j0 = tj * 32;

    int tid = threadIdx.x;
    if (tid < HH * HH) Ws[tid >> 4][tid & 15] = Wpost[tid];
#pragma unroll
    for (int q = 0; q < 2; q++) {
        int idx = q * 256 + tid;         // 512 entries
        int ff = idx >> 5, r = idx & 31;
        invl[ff][r] = 1.0f / g_rsum[(size_t)(b * HH + ff) * NN + i0 + r];
    }
#pragma unroll
    for (int p = 0; p < 16; p++) {
        int idx = p * 256 + tid;         // 4096 float4 loads
        int f = idx >> 8;
        int r = (idx >> 3) & 31;
        int c4 = idx & 7;
        float4 val = *(const float4*)&g_S[((size_t)(b * HH + f) * NN + i0 + r) * NN + j0 + c4 * 4];
        float* ep = &Es[f * 1056 + r * 33 + c4 * 4];   // pad 33 -> conflict-free scalar stores
        ep[0] = val.x; ep[1] = val.y; ep[2] = val.z; ep[3] = val.w;
    }
    __syncthreads();

    int j  = tid >> 3;          // 0..31 (j within tile)
    int i4 = tid & 7;           // 4 consecutive i per thread
    float acc[16][4];
#pragma unroll
    for (int e = 0; e < 16; e++)
#pragma unroll
        for (int u = 0; u < 4; u++) acc[e][u] = 0.f;

#pragma unroll
    for (int f = 0; f < 16; f++) {
        float p0 = Es[f * 1056 + (i4 * 4 + 0) * 33 + j] * invl[f][i4 * 4 + 0];
        float p1 = Es[f * 1056 + (i4 * 4 + 1) * 33 + j] * invl[f][i4 * 4 + 1];
        float p2 = Es[f * 1056 + (i4 * 4 + 2) * 33 + j] * invl[f][i4 * 4 + 2];
        float p3 = Es[f * 1056 + (i4 * 4 + 3) * 33 + j] * invl[f][i4 * 4 + 3];
#pragma unroll
        for (int e = 0; e < 16; e++) {
            float w = Ws[e][f];
            acc[e][0] += w * p0; acc[e][1] += w * p1;
            acc[e][2] += w * p2; acc[e][3] += w * p3;
        }
    }
#pragma unroll
    for (int e = 0; e < 16; e++) {
        float4 vv = make_float4(acc[e][0], acc[e][1], acc[e][2], acc[e][3]);
        *(float4*)&g_PT[((size_t)(b * HH + e) * NN + j0 + j) * NN + i0 + i4 * 4] = vv;
    }
}

// ---------------- K5: out = Pmix @ V  (A read from transposed P^T, causal mask on diag) ----------------
__global__ void __launch_bounds__(128) k_pv(const float* __restrict__ v, float* __restrict__ out)
{
    __shared__ float As[32 * 128];
    __shared__ float Vs[32 * 64];

    int bi = blockIdx.x;
    int ti = 15 - (bi & 15);       // heavy tiles first
    int bh = bi >> 4;
    int i0 = ti * 128;

    const float* Pb = g_PT + (size_t)bh * NN * NN;   // [j][i]
    const float* vb = v    + (size_t)bh * NN * DD;

    int tid = threadIdx.x;         // 128
    int ty = tid >> 3, tx = tid & 7;
    int m0 = ty * 8, d0 = tx * 8;
    float acc[8][8];
#pragma unroll
    for (int r = 0; r < 8; r++)
#pragma unroll
        for (int u = 0; u < 8; u++) acc[r][u] = 0.f;

    int njt = (ti + 1) * 4;
    for (int jt = 0; jt < njt; jt++) {
        int j0 = jt * 32;
        bool diag = (j0 >= i0);
#pragma unroll
        for (int p = 0; p < 8; p++) {
            int idx = p * 128 + tid;
            int r = idx >> 5, c4 = idx & 31;
            float4 val = *(const float4*)&Pb[((size_t)(j0 + r)) * NN + i0 + c4 * 4];
            if (diag) {
                int jg = j0 + r, ig = i0 + c4 * 4;
                if (jg > ig)     val.x = 0.f;
                if (jg > ig + 1) val.y = 0.f;
                if (jg > ig + 2) val.z = 0.f;
                if (jg > ig + 3) val.w = 0.f;
            }
            *(float4*)&As[r * 128 + c4 * 4] = val;
        }
#pragma unroll
        for (int p = 0; p < 4; p++) {
            int idx = p * 128 + tid;
            int r = idx >> 4, c4 = idx & 15;
            *(float4*)&Vs[r * 64 + c4 * 4] = *(const float4*)&vb[((size_t)(j0 + r)) * DD + c4 * 4];
        }
        __syncthreads();
#pragma unroll 4
        for (int jj = 0; jj < 32; jj++) {
            float4 a0 = *(float4*)&As[jj * 128 + m0];
            float4 a1 = *(float4*)&As[jj * 128 + m0 + 4];
            float4 b0 = *(float4*)&Vs[jj * 64 + d0];
            float4 b1 = *(float4*)&Vs[jj * 64 + d0 + 4];
            float a[8] = {a0.x, a0.y, a0.z, a0.w, a1.x, a1.y, a1.z, a1.w};
            float b[8] = {b0.x, b0.y, b0.z, b0.w, b1.x, b1.y, b1.z, b1.w};
#pragma unroll
            for (int r = 0; r < 8; r++)
#pragma unroll
                for (int u = 0; u < 8; u++)
                    acc[r][u] += a[r] * b[u];
        }
        __syncthreads();
    }

    float* ob = out + ((size_t)bh * NN + i0) * DD;
#pragma unroll
    for (int r = 0; r < 8; r++) {
        float4 o0 = make_float4(acc[r][0], acc[r][1], acc[r][2], acc[r][3]);
        float4 o1 = make_float4(acc[r][4], acc[r][5], acc[r][6], acc[r][7]);
        *(float4*)&ob[(size_t)(m0 + r) * DD + d0]     = o0;
        *(float4*)&ob[(size_t)(m0 + r) * DD + d0 + 4] = o1;
    }
}

// ---------------- launcher ----------------
extern "C" void kernel_launch(void* const* d_in, const int* in_sizes, int n_in,
                              void* d_out, int out_size)
{
    const float* q     = (const float*)d_in[0];
    const float* k     = (const float*)d_in[1];
    const float* v     = (const float*)d_in[2];
    const float* Wpre  = (const float*)d_in[3];
    const float* Wpost = (const float*)d_in[4];
    float* out = (float*)d_out;

    cudaFuncSetAttribute(k_qk,   cudaFuncAttributeMaxDynamicSharedMemorySize, 64 * 1024);
    cudaFuncSetAttribute(k_mixp, cudaFuncAttributeMaxDynamicSharedMemorySize, 16 * 1056 * 4);

    // 1) transpose q,k to [b,h,d,n]
    k_transpose<<<dim3(NN / 32, DD / 32, BH), dim3(32, 8)>>>(q, 0);
    k_transpose<<<dim3(NN / 32, DD / 32, BH), dim3(32, 8)>>>(k, 1);

    // 2) head-mix with W_pre
    k_mix<<<(BB * DD * NN) / 256, 256>>>(Wpre);

    // 3) raw scores (lower-tri 128-tiles)
    k_qk<<<dim3(136, BH), 256, 64 * 1024>>>();

    // 4) row softmax (exp in place + row sums)
    k_softmax<<<dim3(NN, BH), 128>>>();

    // 5) normalize + head-mix probs with W_post, write transposed
    k_mixp<<<dim3(2080, BB), 256, 16 * 1056 * 4>>>(Wpost);

    // 6) PV
    k_pv<<<BH * 16, 128>>>(v, out);
}

// round 6
// speedup vs baseline: 1.1145x; 1.1145x over previous
#include <cuda_runtime.h>
#include <math.h>

#define BB 2
#define HH 16
#define NN 2048
#define DD 64
#define BH (BB*HH)
#define SCALE 0.03125f   // 1/(sqrt(16)*sqrt(64))

// ---------------- scratch (static device globals; no allocation) ----------------
__device__ float g_qt[(size_t)BH*DD*NN];       // q transposed [b,h,d,n]
__device__ float g_kt[(size_t)BH*DD*NN];
__device__ float g_qm[(size_t)BH*DD*NN];       // head-mixed q [b,h,d,n]
__device__ float g_km[(size_t)BH*DD*NN];
__device__ float g_S [(size_t)BH*NN*NN];       // unnormalized exp(s - c) (512MB)
__device__ float g_PT[(size_t)BH*NN*NN];       // mixed probs, TRANSPOSED [b,e,j,i] (512MB)
__device__ float g_rsum[(size_t)BH*NN];        // softmax row sums
__device__ float g_psum[(size_t)BH*NN*16];     // per-(row, j-tile) partial sums
__device__ float g_qnorm[(size_t)BH*NN];       // ||q_mixed_i||
__device__ float g_kmax[BH];                   // max_j ||k_mixed_j|| per (b,h)
// NOTE: g_kmax is zero-initialized at module load. atomicMax over identical
// deterministic inputs is idempotent, so no per-launch reset is needed (and
// none would be graph-capture-safe on the legacy stream anyway).

// ---------------- K1a: [b,h,n,d] -> [b,h,d,n] transpose ----------------
__global__ void k_transpose(const float* __restrict__ src, int which)
{
    __shared__ float t[32][33];
    float* dst = which ? g_kt : g_qt;
    int n0 = blockIdx.x * 32;
    int d0 = blockIdx.y * 32;
    int bf = blockIdx.z;
    const float* s = src + (size_t)bf * NN * DD;
    float*       o = dst + (size_t)bf * DD * NN;
    int x = threadIdx.x, y = threadIdx.y;   // 32 x 8
#pragma unroll
    for (int p = 0; p < 4; p++) {
        int r = y + p * 8;
        t[r][x] = s[(size_t)(n0 + r) * DD + d0 + x];
    }
    __syncthreads();
#pragma unroll
    for (int p = 0; p < 4; p++) {
        int r = y + p * 8;
        o[(size_t)(d0 + r) * NN + n0 + x] = t[x][r];
    }
}

// ---------------- K1b: head-mix q,k with W_pre ----------------
__global__ void k_mix(const float* __restrict__ Wpre)
{
    __shared__ float Ws[HH][HH];
    int tid = threadIdx.x;
    if (tid < HH * HH) Ws[tid >> 4][tid & 15] = Wpre[tid];
    __syncthreads();

    size_t idx = (size_t)blockIdx.x * blockDim.x + tid;   // over B*D*N = 262144
    int n = (int)(idx % NN);
    int d = (int)((idx / NN) % DD);
    int b = (int)(idx / ((size_t)NN * DD));

    float xv[HH];
#pragma unroll
    for (int f = 0; f < HH; f++)
        xv[f] = g_qt[((size_t)(b * HH + f) * DD + d) * NN + n];
#pragma unroll
    for (int e = 0; e < HH; e++) {
        float a = 0.f;
#pragma unroll
        for (int f = 0; f < HH; f++) a += Ws[e][f] * xv[f];
        g_qm[((size_t)(b * HH + e) * DD + d) * NN + n] = a;
    }
#pragma unroll
    for (int f = 0; f < HH; f++)
        xv[f] = g_kt[((size_t)(b * HH + f) * DD + d) * NN + n];
#pragma unroll
    for (int e = 0; e < HH; e++) {
        float a = 0.f;
#pragma unroll
        for (int f = 0; f < HH; f++) a += Ws[e][f] * xv[f];
        g_km[((size_t)(b * HH + e) * DD + d) * NN + n] = a;
    }
}

// ---------------- K1c: ||q_i|| per row, max ||k_j|| per head ----------------
__global__ void k_norms()
{
    int bh = blockIdx.y;
    int n  = blockIdx.x * 256 + threadIdx.x;
    const float* qb = g_qm + (size_t)bh * DD * NN;
    const float* kb = g_km + (size_t)bh * DD * NN;
    float sq = 0.f, sk = 0.f;
#pragma unroll
    for (int d = 0; d < DD; d++) {
        float a = qb[(size_t)d * NN + n];
        float b = kb[(size_t)d * NN + n];
        sq += a * a; sk += b * b;
    }
    g_qnorm[(size_t)bh * NN + n] = sqrtf(sq);
    float kn = sqrtf(sk);

    __shared__ float red[256];
    int tid = threadIdx.x;
    red[tid] = kn;
    __syncthreads();
    for (int s = 128; s > 0; s >>= 1) {
        if (tid < s) red[tid] = fmaxf(red[tid], red[tid + s]);
        __syncthreads();
    }
    if (tid == 0)
        atomicMax((int*)&g_kmax[bh], __float_as_int(red[0]));  // all values > 0; idempotent
}

// ---- K2: lower-tri 128x128x64 SGEMM, fused exp(s - c) + partial row sums ----
__global__ void __launch_bounds__(256) k_qk()
{
    extern __shared__ float sm[];
    float* Qs = sm;              // [64][128]
    float* Ks = sm + 64 * 128;   // [64][128]

    int pidx = blockIdx.x;       // 0..135 lower-tri pair (ti>=tj), 16 tiles/dim
    int ti = (int)((sqrtf(8.f * pidx + 1.f) - 1.f) * 0.5f);
    while ((ti + 1) * (ti + 2) / 2 <= pidx) ti++;
    while (ti * (ti + 1) / 2 > pidx) ti--;
    int tj = pidx - ti * (ti + 1) / 2;
    int bh = blockIdx.y;

    const float* qb = g_qm + (size_t)bh * DD * NN + ti * 128;  // [d][n] layout
    const float* kb = g_km + (size_t)bh * DD * NN + tj * 128;

    int tid = threadIdx.x;
    int c4 = tid & 31, rr = tid >> 5;
#pragma unroll
    for (int p = 0; p < 8; p++) {
        int d = p * 8 + rr;
        *(float4*)&Qs[d * 128 + c4 * 4] = *(const float4*)&qb[(size_t)d * NN + c4 * 4];
        *(float4*)&Ks[d * 128 + c4 * 4] = *(const float4*)&kb[(size_t)d * NN + c4 * 4];
    }
    __syncthreads();

    int ty = tid >> 4, tx = tid & 15;
    int m0 = ty * 8, n0 = tx * 8;
    float acc[8][8];
#pragma unroll
    for (int r = 0; r < 8; r++)
#pragma unroll
        for (int u = 0; u < 8; u++) acc[r][u] = 0.f;

#pragma unroll 4
    for (int d = 0; d < 64; d++) {
        float4 a0 = *(float4*)&Qs[d * 128 + m0];
        float4 a1 = *(float4*)&Qs[d * 128 + m0 + 4];
        float4 b0 = *(float4*)&Ks[d * 128 + n0];
        float4 b1 = *(float4*)&Ks[d * 128 + n0 + 4];
        float a[8] = {a0.x, a0.y, a0.z, a0.w, a1.x, a1.y, a1.z, a1.w};
        float b[8] = {b0.x, b0.y, b0.z, b0.w, b1.x, b1.y, b1.z, b1.w};
#pragma unroll
        for (int r = 0; r < 8; r++)
#pragma unroll
            for (int u = 0; u < 8; u++)
                acc[r][u] += a[r] * b[u];
    }

    // Epilogue: exp(s - c_row) with c_row = SCALE*||q_i||*kmax (true upper bound
    // on s -> no overflow; overshoot ~1-2 -> no underflow). Mask j>i on diagonal
    // tiles (also provides zero padding for the mix kernel). Emit per-tile
    // partial row sums (deterministic; no float atomics).
    float kmaxv = g_kmax[bh];
    float qn[8];
#pragma unroll
    for (int r = 0; r < 8; r++)
        qn[r] = g_qnorm[(size_t)bh * NN + ti * 128 + m0 + r];

    float* outp = g_S + (size_t)bh * NN * NN + (size_t)(ti * 128) * NN + tj * 128;
    bool isdiag = (ti == tj);
    float psum[8];
#pragma unroll
    for (int r = 0; r < 8; r++) {
        int ig = m0 + r;                       // row within tile (== global offset diff)
        float c = SCALE * qn[r] * kmaxv;
        float e[8];
#pragma unroll
        for (int u = 0; u < 8; u++) {
            float ev = __expf(acc[r][u] * SCALE - c);
            if (isdiag && (n0 + u) > ig) ev = 0.f;
            e[u] = ev;
        }
        psum[r] = ((e[0] + e[1]) + (e[2] + e[3])) + ((e[4] + e[5]) + (e[6] + e[7]));
        *(float4*)&outp[(size_t)(m0 + r) * NN + n0]     = make_float4(e[0], e[1], e[2], e[3]);
        *(float4*)&outp[(size_t)(m0 + r) * NN + n0 + 4] = make_float4(e[4], e[5], e[6], e[7]);
    }

    __syncthreads();                 // Qs/Ks dead; reuse smem for row-sum reduce
#pragma unroll
    for (int r = 0; r < 8; r++) sm[(m0 + r) * 16 + tx] = psum[r];
    __syncthreads();
    if (tid < 128) {
        const float* rowp = &sm[tid * 16];
        float s = 0.f;
#pragma unroll
        for (int t = 0; t < 16; t++) s += rowp[t];
        g_psum[((size_t)bh * NN + ti * 128 + tid) * 16 + tj] = s;
    }
}

// ---------------- K3: reduce partial row sums ----------------
__global__ void k_rsum()
{
    size_t idx = (size_t)blockIdx.x * 256 + threadIdx.x;   // BH*NN rows
    int i = (int)(idx & (NN - 1));
    int nt = (i >> 7) + 1;                                  // valid j-tiles for this row
    const float* p = g_psum + idx * 16;
    float s = 0.f;
    for (int t = 0; t < nt; t++) s += p[t];
    g_rsum[idx] = s;
}

// ---------------- K4: normalize + 16x16 head-mix of probs, write transposed P^T ----------------
__global__ void __launch_bounds__(256) k_mixp(const float* __restrict__ Wpost)
{
    extern __shared__ float Es[];        // [16][32][33]
    __shared__ float Ws[HH][HH];
    __shared__ float invl[HH][32];

    int pidx = blockIdx.x;               // 0..2079 lower-tri pair over 64 tiles
    int b = blockIdx.y;
    int ti = (int)((sqrtf(8.f * pidx + 1.f) - 1.f) * 0.5f);
    while ((ti + 1) * (ti + 2) / 2 <= pidx) ti++;
    while (ti * (ti + 1) / 2 > pidx) ti--;
    int tj = pidx - ti * (ti + 1) / 2;
    int i0 = ti * 32, j0 = tj * 32;

    int tid = threadIdx.x;
    if (tid < HH * HH) Ws[tid >> 4][tid & 15] = Wpost[tid];
#pragma unroll
    for (int q = 0; q < 2; q++) {
        int idx = q * 256 + tid;         // 512 entries
        int ff = idx >> 5, r = idx & 31;
        invl[ff][r] = 1.0f / g_rsum[(size_t)(b * HH + ff) * NN + i0 + r];
    }
#pragma unroll
    for (int p = 0; p < 16; p++) {
        int idx = p * 256 + tid;         // 4096 float4 loads
        int f = idx >> 8;
        int r = (idx >> 3) & 31;
        int c4 = idx & 7;
        float4 val = *(const float4*)&g_S[((size_t)(b * HH + f) * NN + i0 + r) * NN + j0 + c4 * 4];
        float* ep = &Es[f * 1056 + r * 33 + c4 * 4];   // pad 33 -> conflict-free scalar stores
        ep[0] = val.x; ep[1] = val.y; ep[2] = val.z; ep[3] = val.w;
    }
    __syncthreads();

    int j  = tid >> 3;          // 0..31 (j within tile)
    int i4 = tid & 7;           // 4 consecutive i per thread
    float acc[16][4];
#pragma unroll
    for (int e = 0; e < 16; e++)
#pragma unroll
        for (int u = 0; u < 4; u++) acc[e][u] = 0.f;

#pragma unroll
    for (int f = 0; f < 16; f++) {
        float p0 = Es[f * 1056 + (i4 * 4 + 0) * 33 + j] * invl[f][i4 * 4 + 0];
        float p1 = Es[f * 1056 + (i4 * 4 + 1) * 33 + j] * invl[f][i4 * 4 + 1];
        float p2 = Es[f * 1056 + (i4 * 4 + 2) * 33 + j] * invl[f][i4 * 4 + 2];
        float p3 = Es[f * 1056 + (i4 * 4 + 3) * 33 + j] * invl[f][i4 * 4 + 3];
#pragma unroll
        for (int e = 0; e < 16; e++) {
            float w = Ws[e][f];
            acc[e][0] += w * p0; acc[e][1] += w * p1;
            acc[e][2] += w * p2; acc[e][3] += w * p3;
        }
    }
#pragma unroll
    for (int e = 0; e < 16; e++) {
        float4 vv = make_float4(acc[e][0], acc[e][1], acc[e][2], acc[e][3]);
        *(float4*)&g_PT[((size_t)(b * HH + e) * NN + j0 + j) * NN + i0 + i4 * 4] = vv;
    }
}

// ---------------- K5: out = Pmix @ V  (A read from transposed P^T, causal mask on diag) ----------------
__global__ void __launch_bounds__(128) k_pv(const float* __restrict__ v, float* __restrict__ out)
{
    __shared__ float As[32 * 128];
    __shared__ float Vs[32 * 64];

    int bi = blockIdx.x;
    int ti = 15 - (bi & 15);       // heavy tiles first
    int bh = bi >> 4;
    int i0 = ti * 128;

    const float* Pb = g_PT + (size_t)bh * NN * NN;   // [j][i]
    const float* vb = v    + (size_t)bh * NN * DD;

    int tid = threadIdx.x;         // 128
    int ty = tid >> 3, tx = tid & 7;
    int m0 = ty * 8, d0 = tx * 8;
    float acc[8][8];
#pragma unroll
    for (int r = 0; r < 8; r++)
#pragma unroll
        for (int u = 0; u < 8; u++) acc[r][u] = 0.f;

    int njt = (ti + 1) * 4;
    for (int jt = 0; jt < njt; jt++) {
        int j0 = jt * 32;
        bool diag = (j0 >= i0);
#pragma unroll
        for (int p = 0; p < 8; p++) {
            int idx = p * 128 + tid;
            int r = idx >> 5, c4 = idx & 31;
            float4 val = *(const float4*)&Pb[((size_t)(j0 + r)) * NN + i0 + c4 * 4];
            if (diag) {
                int jg = j0 + r, ig = i0 + c4 * 4;
                if (jg > ig)     val.x = 0.f;
                if (jg > ig + 1) val.y = 0.f;
                if (jg > ig + 2) val.z = 0.f;
                if (jg > ig + 3) val.w = 0.f;
            }
            *(float4*)&As[r * 128 + c4 * 4] = val;
        }
#pragma unroll
        for (int p = 0; p < 4; p++) {
            int idx = p * 128 + tid;
            int r = idx >> 4, c4 = idx & 15;
            *(float4*)&Vs[r * 64 + c4 * 4] = *(const float4*)&vb[((size_t)(j0 + r)) * DD + c4 * 4];
        }
        __syncthreads();
#pragma unroll 4
        for (int jj = 0; jj < 32; jj++) {
            float4 a0 = *(float4*)&As[jj * 128 + m0];
            float4 a1 = *(float4*)&As[jj * 128 + m0 + 4];
            float4 b0 = *(float4*)&Vs[jj * 64 + d0];
            float4 b1 = *(float4*)&Vs[jj * 64 + d0 + 4];
            float a[8] = {a0.x, a0.y, a0.z, a0.w, a1.x, a1.y, a1.z, a1.w};
            float b[8] = {b0.x, b0.y, b0.z, b0.w, b1.x, b1.y, b1.z, b1.w};
#pragma unroll
            for (int r = 0; r < 8; r++)
#pragma unroll
                for (int u = 0; u < 8; u++)
                    acc[r][u] += a[r] * b[u];
        }
        __syncthreads();
    }

    float* ob = out + ((size_t)bh * NN + i0) * DD;
#pragma unroll
    for (int r = 0; r < 8; r++) {
        float4 o0 = make_float4(acc[r][0], acc[r][1], acc[r][2], acc[r][3]);
        float4 o1 = make_float4(acc[r][4], acc[r][5], acc[r][6], acc[r][7]);
        *(float4*)&ob[(size_t)(m0 + r) * DD + d0]     = o0;
        *(float4*)&ob[(size_t)(m0 + r) * DD + d0 + 4] = o1;
    }
}

// ---------------- launcher ----------------
extern "C" void kernel_launch(void* const* d_in, const int* in_sizes, int n_in,
                              void* d_out, int out_size)
{
    const float* q     = (const float*)d_in[0];
    const float* k     = (const float*)d_in[1];
    const float* v     = (const float*)d_in[2];
    const float* Wpre  = (const float*)d_in[3];
    const float* Wpost = (const float*)d_in[4];
    float* out = (float*)d_out;

    cudaFuncSetAttribute(k_qk,   cudaFuncAttributeMaxDynamicSharedMemorySize, 64 * 1024);
    cudaFuncSetAttribute(k_mixp, cudaFuncAttributeMaxDynamicSharedMemorySize, 16 * 1056 * 4);

    // 1) transpose q,k to [b,h,d,n]
    k_transpose<<<dim3(NN / 32, DD / 32, BH), dim3(32, 8)>>>(q, 0);
    k_transpose<<<dim3(NN / 32, DD / 32, BH), dim3(32, 8)>>>(k, 1);

    // 2) head-mix with W_pre
    k_mix<<<(BB * DD * NN) / 256, 256>>>(Wpre);

    // 2b) row norms of mixed q, per-head max norm of mixed k
    k_norms<<<dim3(NN / 256, BH), 256>>>();

    // 3) scores + fused exp(s - c) + partial row sums (lower-tri 128-tiles)
    k_qk<<<dim3(136, BH), 256, 64 * 1024>>>();

    // 3b) reduce partial row sums
    k_rsum<<<(BH * NN) / 256, 256>>>();

    // 4) normalize + head-mix probs with W_post, write transposed
    k_mixp<<<dim3(2080, BB), 256, 16 * 1056 * 4>>>(Wpost);

    // 5) PV
    k_pv<<<BH * 16, 128>>>(v, out);
}

// round 7
// speedup vs baseline: 1.2285x; 1.1024x over previous
#include <cuda_runtime.h>
#include <cuda_fp16.h>
#include <math.h>

#define BB 2
#define HH 16
#define NN 2048
#define DD 64
#define BH (BB*HH)
#define SCALE 0.03125f   // 1/(sqrt(16)*sqrt(64))

// ---------------- scratch (static device globals; no allocation) ----------------
__device__ float  g_qt[(size_t)BH*DD*NN];      // q transposed [b,h,d,n]
__device__ float  g_kt[(size_t)BH*DD*NN];
__device__ float  g_qm[(size_t)BH*DD*NN];      // head-mixed q [b,h,d,n]
__device__ float  g_km[(size_t)BH*DD*NN];
__device__ __half g_S [(size_t)BH*NN*NN];      // unnormalized exp(s - c), fp16 (256MB)
__device__ __half g_PT[(size_t)BH*NN*NN];      // mixed probs, TRANSPOSED [b,e,j,i], fp16 (256MB)
__device__ float  g_rsum[(size_t)BH*NN];       // softmax row sums
__device__ float  g_psum[(size_t)BH*NN*16];    // per-(row, j-tile) partial sums
__device__ float  g_qnorm[(size_t)BH*NN];      // ||q_mixed_i||
__device__ float  g_kmax[BH];                  // max_j ||k_mixed_j|| per (b,h)
// g_kmax: zero-initialized at load; atomicMax over identical deterministic
// inputs is idempotent, so no per-launch reset needed (graph-capture safe).

// ---------------- half pack/unpack helpers (storage only; all math fp32) ----------------
__device__ __forceinline__ unsigned h2u(float a, float b) {
    __half2 h = __floats2half2_rn(a, b);
    return *(unsigned*)&h;
}
__device__ __forceinline__ float4 u2f4(uint2 u) {
    __half2 h0 = *(__half2*)&u.x;
    __half2 h1 = *(__half2*)&u.y;
    float2 f0 = __half22float2(h0);
    float2 f1 = __half22float2(h1);
    return make_float4(f0.x, f0.y, f1.x, f1.y);
}

// ---------------- K1a: [b,h,n,d] -> [b,h,d,n] transpose ----------------
__global__ void k_transpose(const float* __restrict__ src, int which)
{
    __shared__ float t[32][33];
    float* dst = which ? g_kt : g_qt;
    int n0 = blockIdx.x * 32;
    int d0 = blockIdx.y * 32;
    int bf = blockIdx.z;
    const float* s = src + (size_t)bf * NN * DD;
    float*       o = dst + (size_t)bf * DD * NN;
    int x = threadIdx.x, y = threadIdx.y;   // 32 x 8
#pragma unroll
    for (int p = 0; p < 4; p++) {
        int r = y + p * 8;
        t[r][x] = s[(size_t)(n0 + r) * DD + d0 + x];
    }
    __syncthreads();
#pragma unroll
    for (int p = 0; p < 4; p++) {
        int r = y + p * 8;
        o[(size_t)(d0 + r) * NN + n0 + x] = t[x][r];
    }
}

// ---------------- K1b: head-mix q,k with W_pre ----------------
__global__ void k_mix(const float* __restrict__ Wpre)
{
    __shared__ float Ws[HH][HH];
    int tid = threadIdx.x;
    if (tid < HH * HH) Ws[tid >> 4][tid & 15] = Wpre[tid];
    __syncthreads();

    size_t idx = (size_t)blockIdx.x * blockDim.x + tid;   // over B*D*N = 262144
    int n = (int)(idx % NN);
    int d = (int)((idx / NN) % DD);
    int b = (int)(idx / ((size_t)NN * DD));

    float xv[HH];
#pragma unroll
    for (int f = 0; f < HH; f++)
        xv[f] = g_qt[((size_t)(b * HH + f) * DD + d) * NN + n];
#pragma unroll
    for (int e = 0; e < HH; e++) {
        float a = 0.f;
#pragma unroll
        for (int f = 0; f < HH; f++) a += Ws[e][f] * xv[f];
        g_qm[((size_t)(b * HH + e) * DD + d) * NN + n] = a;
    }
#pragma unroll
    for (int f = 0; f < HH; f++)
        xv[f] = g_kt[((size_t)(b * HH + f) * DD + d) * NN + n];
#pragma unroll
    for (int e = 0; e < HH; e++) {
        float a = 0.f;
#pragma unroll
        for (int f = 0; f < HH; f++) a += Ws[e][f] * xv[f];
        g_km[((size_t)(b * HH + e) * DD + d) * NN + n] = a;
    }
}

// ---------------- K1c: ||q_i|| per row, max ||k_j|| per head ----------------
__global__ void k_norms()
{
    int bh = blockIdx.y;
    int n  = blockIdx.x * 256 + threadIdx.x;
    const float* qb = g_qm + (size_t)bh * DD * NN;
    const float* kb = g_km + (size_t)bh * DD * NN;
    float sq = 0.f, sk = 0.f;
#pragma unroll
    for (int d = 0; d < DD; d++) {
        float a = qb[(size_t)d * NN + n];
        float b = kb[(size_t)d * NN + n];
        sq += a * a; sk += b * b;
    }
    g_qnorm[(size_t)bh * NN + n] = sqrtf(sq);
    float kn = sqrtf(sk);

    __shared__ float red[256];
    int tid = threadIdx.x;
    red[tid] = kn;
    __syncthreads();
    for (int s = 128; s > 0; s >>= 1) {
        if (tid < s) red[tid] = fmaxf(red[tid], red[tid + s]);
        __syncthreads();
    }
    if (tid == 0)
        atomicMax((int*)&g_kmax[bh], __float_as_int(red[0]));  // all values > 0; idempotent
}

// ---- K2: lower-tri 128x128x64 SGEMM, 8x16 microtile, fused exp(s-c) + partial sums ----
// 128 threads; thread (ty,tx) computes rows m0..m0+7, cols {tx*4 + c*32 + u}.
// Column mapping tx*4 + c*32 keeps all shared B-loads conflict-free
// (8 lanes x consecutive 16B lines per chunk).
__global__ void __launch_bounds__(128) k_qk()
{
    extern __shared__ float sm[];
    float* Qs = sm;              // [64][128]
    float* Ks = sm + 64 * 128;   // [64][128]

    int pidx = blockIdx.x;       // 0..135 lower-tri pair (ti>=tj), 16 tiles/dim
    int ti = (int)((sqrtf(8.f * pidx + 1.f) - 1.f) * 0.5f);
    while ((ti + 1) * (ti + 2) / 2 <= pidx) ti++;
    while (ti * (ti + 1) / 2 > pidx) ti--;
    int tj = pidx - ti * (ti + 1) / 2;
    int bh = blockIdx.y;

    const float* qb = g_qm + (size_t)bh * DD * NN + ti * 128;  // [d][n] layout
    const float* kb = g_km + (size_t)bh * DD * NN + tj * 128;

    int tid = threadIdx.x;
    int c4 = tid & 31, rr = tid >> 5;    // rr 0..3
#pragma unroll
    for (int p = 0; p < 16; p++) {
        int d = p * 4 + rr;
        *(float4*)&Qs[d * 128 + c4 * 4] = *(const float4*)&qb[(size_t)d * NN + c4 * 4];
        *(float4*)&Ks[d * 128 + c4 * 4] = *(const float4*)&kb[(size_t)d * NN + c4 * 4];
    }
    __syncthreads();

    int ty = tid >> 3, tx = tid & 7;     // ty 0..15, tx 0..7
    int m0 = ty * 8;
    float acc[8][16];
#pragma unroll
    for (int r = 0; r < 8; r++)
#pragma unroll
        for (int u = 0; u < 16; u++) acc[r][u] = 0.f;

#pragma unroll 2
    for (int d = 0; d < 64; d++) {
        float4 a0 = *(float4*)&Qs[d * 128 + m0];
        float4 a1 = *(float4*)&Qs[d * 128 + m0 + 4];
        float a[8] = {a0.x, a0.y, a0.z, a0.w, a1.x, a1.y, a1.z, a1.w};
        float b[16];
#pragma unroll
        for (int c = 0; c < 4; c++) {
            float4 bv = *(float4*)&Ks[d * 128 + tx * 4 + c * 32];
            b[c * 4 + 0] = bv.x; b[c * 4 + 1] = bv.y;
            b[c * 4 + 2] = bv.z; b[c * 4 + 3] = bv.w;
        }
#pragma unroll
        for (int r = 0; r < 8; r++)
#pragma unroll
            for (int u = 0; u < 16; u++)
                acc[r][u] += a[r] * b[u];
    }

    // Epilogue: exp(s - c_row), c_row = SCALE*||q_i||*kmax (true upper bound ->
    // no overflow; overshoot ~1-2 -> no underflow). Mask j>i on diagonal tiles.
    // Store fp16; emit per-tile partial row sums (fp32, deterministic).
    float kmaxv = g_kmax[bh];
    float qn[8];
#pragma unroll
    for (int r = 0; r < 8; r++)
        qn[r] = g_qnorm[(size_t)bh * NN + ti * 128 + m0 + r];

    __half* outp = g_S + (size_t)bh * NN * NN + (size_t)(ti * 128) * NN + tj * 128;
    bool isdiag = (ti == tj);
    float psum[8];
#pragma unroll
    for (int r = 0; r < 8; r++) {
        int ig = m0 + r;                       // row within tile
        float c = SCALE * qn[r] * kmaxv;
        float e[16];
#pragma unroll
        for (int cc = 0; cc < 4; cc++)
#pragma unroll
            for (int u = 0; u < 4; u++) {
                int col = tx * 4 + cc * 32 + u;
                float ev = __expf(acc[r][cc * 4 + u] * SCALE - c);
                if (isdiag && col > ig) ev = 0.f;
                e[cc * 4 + u] = ev;
            }
        float s = 0.f;
#pragma unroll
        for (int u = 0; u < 16; u++) s += e[u];
        psum[r] = s;
#pragma unroll
        for (int cc = 0; cc < 4; cc++) {
            uint2 w = make_uint2(h2u(e[cc * 4 + 0], e[cc * 4 + 1]),
                                 h2u(e[cc * 4 + 2], e[cc * 4 + 3]));
            *(uint2*)&outp[(size_t)(m0 + r) * NN + tx * 4 + cc * 32] = w;
        }
    }

    __syncthreads();                 // Qs/Ks dead; reuse smem for row-sum reduce
#pragma unroll
    for (int r = 0; r < 8; r++) sm[(m0 + r) * 8 + tx] = psum[r];
    __syncthreads();
    {
        const float* rowp = &sm[tid * 8];   // 128 threads, 128 rows
        float s = 0.f;
#pragma unroll
        for (int t = 0; t < 8; t++) s += rowp[t];
        g_psum[((size_t)bh * NN + ti * 128 + tid) * 16 + tj] = s;
    }
}

// ---------------- K3: reduce partial row sums ----------------
__global__ void k_rsum()
{
    size_t idx = (size_t)blockIdx.x * 256 + threadIdx.x;   // BH*NN rows
    int i = (int)(idx & (NN - 1));
    int nt = (i >> 7) + 1;                                  // valid j-tiles for this row
    const float* p = g_psum + idx * 16;
    float s = 0.f;
    for (int t = 0; t < nt; t++) s += p[t];
    g_rsum[idx] = s;
}

// ---------------- K4: normalize + 16x16 head-mix of probs, write transposed P^T (fp16) ----------------
__global__ void __launch_bounds__(256) k_mixp(const float* __restrict__ Wpost)
{
    extern __shared__ float Es[];        // [16][32][33]
    __shared__ float Ws[HH][HH];
    __shared__ float invl[HH][32];

    int pidx = blockIdx.x;               // 0..2079 lower-tri pair over 64 tiles
    int b = blockIdx.y;
    int ti = (int)((sqrtf(8.f * pidx + 1.f) - 1.f) * 0.5f);
    while ((ti + 1) * (ti + 2) / 2 <= pidx) ti++;
    while (ti * (ti + 1) / 2 > pidx) ti--;
    int tj = pidx - ti * (ti + 1) / 2;
    int i0 = ti * 32, j0 = tj * 32;

    int tid = threadIdx.x;
    if (tid < HH * HH) Ws[tid >> 4][tid & 15] = Wpost[tid];
#pragma unroll
    for (int q = 0; q < 2; q++) {
        int idx = q * 256 + tid;         // 512 entries
        int ff = idx >> 5, r = idx & 31;
        invl[ff][r] = 1.0f / g_rsum[(size_t)(b * HH + ff) * NN + i0 + r];
    }
#pragma unroll
    for (int p = 0; p < 16; p++) {
        int idx = p * 256 + tid;         // 4096 x (4 halfs = 8B) loads
        int f = idx >> 8;
        int r = (idx >> 3) & 31;
        int c4 = idx & 7;
        uint2 uv = *(const uint2*)&g_S[((size_t)(b * HH + f) * NN + i0 + r) * NN + j0 + c4 * 4];
        float4 val = u2f4(uv);
        float* ep = &Es[f * 1056 + r * 33 + c4 * 4];   // pad 33 -> conflict-free scalar stores
        ep[0] = val.x; ep[1] = val.y; ep[2] = val.z; ep[3] = val.w;
    }
    __syncthreads();

    int j  = tid >> 3;          // 0..31 (j within tile)
    int i4 = tid & 7;           // 4 consecutive i per thread
    float acc[16][4];
#pragma unroll
    for (int e = 0; e < 16; e++)
#pragma unroll
        for (int u = 0; u < 4; u++) acc[e][u] = 0.f;

#pragma unroll
    for (int f = 0; f < 16; f++) {
        float p0 = Es[f * 1056 + (i4 * 4 + 0) * 33 + j] * invl[f][i4 * 4 + 0];
        float p1 = Es[f * 1056 + (i4 * 4 + 1) * 33 + j] * invl[f][i4 * 4 + 1];
        float p2 = Es[f * 1056 + (i4 * 4 + 2) * 33 + j] * invl[f][i4 * 4 + 2];
        float p3 = Es[f * 1056 + (i4 * 4 + 3) * 33 + j] * invl[f][i4 * 4 + 3];
#pragma unroll
        for (int e = 0; e < 16; e++) {
            float w = Ws[e][f];
            acc[e][0] += w * p0; acc[e][1] += w * p1;
            acc[e][2] += w * p2; acc[e][3] += w * p3;
        }
    }
#pragma unroll
    for (int e = 0; e < 16; e++) {
        uint2 w = make_uint2(h2u(acc[e][0], acc[e][1]), h2u(acc[e][2], acc[e][3]));
        *(uint2*)&g_PT[((size_t)(b * HH + e) * NN + j0 + j) * NN + i0 + i4 * 4] = w;
    }
}

// ---------------- K5: out = Pmix @ V (A from fp16 P^T; conflict-free d-mapping) ----------------
__global__ void __launch_bounds__(128) k_pv(const float* __restrict__ v, float* __restrict__ out)
{
    __shared__ float As[32 * 128];
    __shared__ float Vs[32 * 64];

    int bi = blockIdx.x;
    int ti = 15 - (bi & 15);       // heavy tiles first
    int bh = bi >> 4;
    int i0 = ti * 128;

    const __half* Pb = g_PT + (size_t)bh * NN * NN;   // [j][i], fp16
    const float*  vb = v    + (size_t)bh * NN * DD;

    int tid = threadIdx.x;         // 128
    int ty = tid >> 3, tx = tid & 7;
    int m0 = ty * 8;
    float acc[8][8];
#pragma unroll
    for (int r = 0; r < 8; r++)
#pragma unroll
        for (int u = 0; u < 8; u++) acc[r][u] = 0.f;

    int njt = (ti + 1) * 4;
    for (int jt = 0; jt < njt; jt++) {
        int j0 = jt * 32;
        bool diag = (j0 >= i0);
#pragma unroll
        for (int p = 0; p < 8; p++) {
            int idx = p * 128 + tid;
            int r = idx >> 5, c4 = idx & 31;
            uint2 uv = *(const uint2*)&Pb[((size_t)(j0 + r)) * NN + i0 + c4 * 4];
            float4 val = u2f4(uv);
            if (diag) {
                int jg = j0 + r, ig = i0 + c4 * 4;
                if (jg > ig)     val.x = 0.f;
                if (jg > ig + 1) val.y = 0.f;
                if (jg > ig + 2) val.z = 0.f;
                if (jg > ig + 3) val.w = 0.f;
            }
            *(float4*)&As[r * 128 + c4 * 4] = val;
        }
#pragma unroll
        for (int p = 0; p < 4; p++) {
            int idx = p * 128 + tid;
            int r = idx >> 4, c4 = idx & 15;
            *(float4*)&Vs[r * 64 + c4 * 4] = *(const float4*)&vb[((size_t)(j0 + r)) * DD + c4 * 4];
        }
        __syncthreads();
#pragma unroll 4
        for (int jj = 0; jj < 32; jj++) {
            float4 a0 = *(float4*)&As[jj * 128 + m0];
            float4 a1 = *(float4*)&As[jj * 128 + m0 + 4];
            float4 b0 = *(float4*)&Vs[jj * 64 + tx * 4];        // conflict-free:
            float4 b1 = *(float4*)&Vs[jj * 64 + tx * 4 + 32];   // 8 lanes x 16B lines
            float a[8] = {a0.x, a0.y, a0.z, a0.w, a1.x, a1.y, a1.z, a1.w};
            float b[8] = {b0.x, b0.y, b0.z, b0.w, b1.x, b1.y, b1.z, b1.w};
#pragma unroll
            for (int r = 0; r < 8; r++)
#pragma unroll
                for (int u = 0; u < 8; u++)
                    acc[r][u] += a[r] * b[u];
        }
        __syncthreads();
    }

    float* ob = out + ((size_t)bh * NN + i0) * DD;
#pragma unroll
    for (int r = 0; r < 8; r++) {
        float4 o0 = make_float4(acc[r][0], acc[r][1], acc[r][2], acc[r][3]);
        float4 o1 = make_float4(acc[r][4], acc[r][5], acc[r][6], acc[r][7]);
        *(float4*)&ob[(size_t)(m0 + r) * DD + tx * 4]      = o0;
        *(float4*)&ob[(size_t)(m0 + r) * DD + tx * 4 + 32] = o1;
    }
}

// ---------------- launcher ----------------
extern "C" void kernel_launch(void* const* d_in, const int* in_sizes, int n_in,
                              void* d_out, int out_size)
{
    const float* q     = (const float*)d_in[0];
    const float* k     = (const float*)d_in[1];
    const float* v     = (const float*)d_in[2];
    const float* Wpre  = (const float*)d_in[3];
    const float* Wpost = (const float*)d_in[4];
    float* out = (float*)d_out;

    cudaFuncSetAttribute(k_qk,   cudaFuncAttributeMaxDynamicSharedMemorySize, 64 * 1024);
    cudaFuncSetAttribute(k_mixp, cudaFuncAttributeMaxDynamicSharedMemorySize, 16 * 1056 * 4);

    // 1) transpose q,k to [b,h,d,n]
    k_transpose<<<dim3(NN / 32, DD / 32, BH), dim3(32, 8)>>>(q, 0);
    k_transpose<<<dim3(NN / 32, DD / 32, BH), dim3(32, 8)>>>(k, 1);

    // 2) head-mix with W_pre
    k_mix<<<(BB * DD * NN) / 256, 256>>>(Wpre);

    // 2b) row norms of mixed q, per-head max norm of mixed k
    k_norms<<<dim3(NN / 256, BH), 256>>>();

    // 3) scores + fused exp(s - c) + partial row sums (lower-tri 128-tiles, fp16 out)
    k_qk<<<dim3(136, BH), 128, 64 * 1024>>>();

    // 3b) reduce partial row sums
    k_rsum<<<(BH * NN) / 256, 256>>>();

    // 4) normalize + head-mix probs with W_post, write transposed (fp16)
    k_mixp<<<dim3(2080, BB), 256, 16 * 1056 * 4>>>(Wpost);

    // 5) PV
    k_pv<<<BH * 16, 128>>>(v, out);
}

// round 9
// speedup vs baseline: 2.8570x; 2.3256x over previous
#include <cuda_runtime.h>
#include <cuda_fp16.h>
#include <math.h>

#define BB 2
#define HH 16
#define NN 2048
#define DD 64
#define BH (BB*HH)
#define SCALE 0.03125f   // 1/(sqrt(16)*sqrt(64))

// ---------------- scratch (static device globals; no allocation) ----------------
__device__ __half g_qh[(size_t)BH*NN*DD];      // head-mixed q, fp16 [b,e,n,d]
__device__ __half g_kh[(size_t)BH*NN*DD];      // head-mixed k, fp16 [b,e,n,d]
__device__ __half g_vh[(size_t)BH*NN*DD];      // v, fp16 [b,h,n,d]
__device__ __half g_S [(size_t)BH*NN*NN];      // unnormalized exp(s - c), fp16 (256MB)
__device__ __half g_P [(size_t)BH*NN*NN];      // mixed probs [b,e,i,j], fp16 (256MB)
__device__ float  g_rsum[(size_t)BH*NN];       // softmax row sums
__device__ float  g_psum[(size_t)BH*NN*16];    // per-(row, j-tile) partial sums
__device__ float  g_qnorm[(size_t)BH*NN];      // ||q_mixed_i|| (of fp16 values)
__device__ float  g_kmax[BH];                  // max_j ||k_mixed_j|| per (b,h)
// g_kmax: zero-initialized at load; atomicMax over identical deterministic
// inputs is idempotent -> no per-launch reset needed (graph-capture safe).

// ---------------- helpers ----------------
__device__ __forceinline__ unsigned h2u(float a, float b) {
    __half2 h = __floats2half2_rn(a, b);
    return *(unsigned*)&h;
}
__device__ __forceinline__ float4 u2f4(uint2 u) {
    float2 f0 = __half22float2(*(__half2*)&u.x);
    float2 f1 = __half22float2(*(__half2*)&u.y);
    return make_float4(f0.x, f0.y, f1.x, f1.y);
}
__device__ __forceinline__ unsigned sm_addr(const void* p) {
    return (unsigned)__cvta_generic_to_shared(p);
}
__device__ __forceinline__ void ldsm_x4(unsigned* r, unsigned a) {
    asm volatile("ldmatrix.sync.aligned.m8n8.x4.shared.b16 {%0,%1,%2,%3}, [%4];\n"
        : "=r"(r[0]), "=r"(r[1]), "=r"(r[2]), "=r"(r[3]) : "r"(a));
}
__device__ __forceinline__ void ldsm_x2(unsigned* r, unsigned a) {
    asm volatile("ldmatrix.sync.aligned.m8n8.x2.shared.b16 {%0,%1}, [%2];\n"
        : "=r"(r[0]), "=r"(r[1]) : "r"(a));
}
__device__ __forceinline__ void ldsm_x2t(unsigned* r, unsigned a) {
    asm volatile("ldmatrix.sync.aligned.m8n8.x2.trans.shared.b16 {%0,%1}, [%2];\n"
        : "=r"(r[0]), "=r"(r[1]) : "r"(a));
}
__device__ __forceinline__ void mma16816(float* c, const unsigned* a, const unsigned* b) {
    asm volatile(
        "mma.sync.aligned.m16n8k16.row.col.f32.f16.f16.f32 "
        "{%0,%1,%2,%3}, {%4,%5,%6,%7}, {%8,%9}, {%0,%1,%2,%3};\n"
        : "+f"(c[0]), "+f"(c[1]), "+f"(c[2]), "+f"(c[3])
        : "r"(a[0]), "r"(a[1]), "r"(a[2]), "r"(a[3]), "r"(b[0]), "r"(b[1]));
}

// ---------------- K1: head-mix q,k with W_pre, straight from input layout, fp16 out ----------------
__global__ void k_mix(const float* __restrict__ q, const float* __restrict__ k,
                      const float* __restrict__ Wpre)
{
    __shared__ float Ws[HH][HH];
    int tid = threadIdx.x;
    if (tid < HH * HH) Ws[tid >> 4][tid & 15] = Wpre[tid];
    __syncthreads();

    size_t idx = (size_t)blockIdx.x * 256 + tid;          // over B*N*D = 262144 sites
    int d = (int)(idx % DD);
    int n = (int)((idx / DD) % NN);
    int b = (int)(idx / ((size_t)NN * DD));
    size_t site = ((size_t)n) * DD + d;

    float xv[HH];
#pragma unroll
    for (int f = 0; f < HH; f++)
        xv[f] = q[((size_t)(b * HH + f) * NN) * DD + site];
#pragma unroll
    for (int e = 0; e < HH; e++) {
        float a = 0.f;
#pragma unroll
        for (int f = 0; f < HH; f++) a += Ws[e][f] * xv[f];
        g_qh[((size_t)(b * HH + e) * NN) * DD + site] = __float2half_rn(a);
    }
#pragma unroll
    for (int f = 0; f < HH; f++)
        xv[f] = k[((size_t)(b * HH + f) * NN) * DD + site];
#pragma unroll
    for (int e = 0; e < HH; e++) {
        float a = 0.f;
#pragma unroll
        for (int f = 0; f < HH; f++) a += Ws[e][f] * xv[f];
        g_kh[((size_t)(b * HH + e) * NN) * DD + site] = __float2half_rn(a);
    }
}

// ---------------- K1b: v -> fp16 ----------------
__global__ void k_vh(const float* __restrict__ v)
{
    size_t i = ((size_t)blockIdx.x * 256 + threadIdx.x) * 4;
    float4 f = *(const float4*)&v[i];
    *(uint2*)&g_vh[i] = make_uint2(h2u(f.x, f.y), h2u(f.z, f.w));
}

// ---------------- K1c: ||q_i|| per row (of fp16 values), max ||k_j|| per head ----------------
__global__ void k_norms()
{
    int bh = blockIdx.y;
    int n  = blockIdx.x * 256 + threadIdx.x;
    const __half* qb = g_qh + ((size_t)bh * NN + n) * DD;
    const __half* kb = g_kh + ((size_t)bh * NN + n) * DD;
    float sq = 0.f, sk = 0.f;
#pragma unroll
    for (int d = 0; d < DD; d += 2) {
        float2 a = __half22float2(*(const __half2*)&qb[d]);
        float2 b = __half22float2(*(const __half2*)&kb[d]);
        sq += a.x * a.x + a.y * a.y;
        sk += b.x * b.x + b.y * b.y;
    }
    g_qnorm[(size_t)bh * NN + n] = sqrtf(sq);
    float kn = sqrtf(sk);

    __shared__ float red[256];
    int tid = threadIdx.x;
    red[tid] = kn;
    __syncthreads();
    for (int s = 128; s > 0; s >>= 1) {
        if (tid < s) red[tid] = fmaxf(red[tid], red[tid + s]);
        __syncthreads();
    }
    if (tid == 0)
        atomicMax((int*)&g_kmax[bh], __float_as_int(red[0]));  // all > 0; idempotent
}

// ---------------- K1d: zero strictly-upper 32-tiles inside diagonal 128-blocks of g_P ----------------
__global__ void k_zerop()
{
    int be  = blockIdx.x >> 4;          // 0..31 (b*HH+e)
    int blk = blockIdx.x & 15;          // diag 128-block
    int r = threadIdx.x >> 3, c = threadIdx.x & 7;
    const int pa[6] = {0,0,0,1,1,2}, pb[6] = {1,2,3,2,3,3};
#pragma unroll
    for (int u = 0; u < 6; u++) {
        size_t off = ((size_t)be * NN + blk * 128 + pa[u] * 32 + r) * NN
                   + blk * 128 + pb[u] * 32 + c * 4;
        *(uint2*)&g_P[off] = make_uint2(0u, 0u);
    }
}

// ---- K2: lower-tri 128x128x64 tensor-core GEMM + fused exp(s-c) + partial row sums ----
__global__ void __launch_bounds__(256) k_qk()
{
    __shared__ __half Qs[128 * 72];
    __shared__ __half Ks[128 * 72];
    __shared__ float  psumS[128][4];

    int pidx = blockIdx.x;       // 0..135 lower-tri pair (ti>=tj)
    int ti = (int)((sqrtf(8.f * pidx + 1.f) - 1.f) * 0.5f);
    while ((ti + 1) * (ti + 2) / 2 <= pidx) ti++;
    while (ti * (ti + 1) / 2 > pidx) ti--;
    int tj = pidx - ti * (ti + 1) / 2;
    int bh = blockIdx.y;

    const __half* qb = g_qh + ((size_t)bh * NN + ti * 128) * DD;
    const __half* kb = g_kh + ((size_t)bh * NN + tj * 128) * DD;

    int tid = threadIdx.x;
#pragma unroll
    for (int p = 0; p < 4; p++) {
        int idx = p * 256 + tid;            // 1024 = 128 rows x 8 chunks
        int r = idx >> 3, c8 = idx & 7;
        *(uint4*)&Qs[r * 72 + c8 * 8] = *(const uint4*)&qb[r * 64 + c8 * 8];
        *(uint4*)&Ks[r * 72 + c8 * 8] = *(const uint4*)&kb[r * 64 + c8 * 8];
    }
    __syncthreads();

    int w = tid >> 5, l = tid & 31;
    int wm0 = (w >> 2) * 64;                // warp rows
    int wn0 = (w & 3) * 32;                 // warp cols
    unsigned qbase = sm_addr(Qs), kbase = sm_addr(Ks);

    float acc[4][4][4];
#pragma unroll
    for (int mi = 0; mi < 4; mi++)
#pragma unroll
        for (int ni = 0; ni < 4; ni++)
#pragma unroll
            for (int u = 0; u < 4; u++) acc[mi][ni][u] = 0.f;

#pragma unroll
    for (int kk = 0; kk < 64; kk += 16) {
        unsigned a[4][4], b[4][2];
#pragma unroll
        for (int mi = 0; mi < 4; mi++)
            ldsm_x4(a[mi], qbase + ((wm0 + mi * 16 + (l & 15)) * 72 + kk + (l >> 4) * 8) * 2);
#pragma unroll
        for (int ni = 0; ni < 4; ni++)
            ldsm_x2(b[ni], kbase + ((wn0 + ni * 8 + (l & 7)) * 72 + kk + ((l >> 3) & 1) * 8) * 2);
#pragma unroll
        for (int mi = 0; mi < 4; mi++)
#pragma unroll
            for (int ni = 0; ni < 4; ni++)
                mma16816(acc[mi][ni], a[mi], b[ni]);
    }

    // Epilogue: exp(s - c_row), c_row = SCALE*||q_i||*kmax (true upper bound).
    float kmaxv = g_kmax[bh];
    bool isdiag = (ti == tj);
    int grp = l >> 2, qd = l & 3;
    __half* Sb = g_S + (size_t)bh * NN * NN;

#pragma unroll
    for (int mi = 0; mi < 4; mi++) {
#pragma unroll
        for (int h = 0; h < 2; h++) {
            int row = wm0 + mi * 16 + grp + h * 8;          // local row in tile
            float cb = SCALE * g_qnorm[(size_t)bh * NN + ti * 128 + row] * kmaxv;
            float rsum = 0.f;
#pragma unroll
            for (int ni = 0; ni < 4; ni++) {
                int col = wn0 + ni * 8 + qd * 2;            // local col
                float e0 = __expf(acc[mi][ni][2 * h]     * SCALE - cb);
                float e1 = __expf(acc[mi][ni][2 * h + 1] * SCALE - cb);
                if (isdiag && col     > row) e0 = 0.f;
                if (isdiag && col + 1 > row) e1 = 0.f;
                rsum += e0 + e1;
                *(unsigned*)&Sb[(size_t)(ti * 128 + row) * NN + tj * 128 + col] = h2u(e0, e1);
            }
            // reduce rsum across the 4 lanes sharing this row (same l>>2)
            rsum += __shfl_xor_sync(0xffffffff, rsum, 1);
            rsum += __shfl_xor_sync(0xffffffff, rsum, 2);
            if (qd == 0) psumS[row][w & 3] = rsum;
        }
    }
    __syncthreads();
    if (tid < 128) {
        float s = psumS[tid][0] + psumS[tid][1] + psumS[tid][2] + psumS[tid][3];
        g_psum[((size_t)bh * NN + ti * 128 + tid) * 16 + tj] = s;
    }
}

// ---------------- K3: reduce partial row sums ----------------
__global__ void k_rsum()
{
    size_t idx = (size_t)blockIdx.x * 256 + threadIdx.x;   // BH*NN rows
    int i = (int)(idx & (NN - 1));
    int nt = (i >> 7) + 1;
    const float* p = g_psum + idx * 16;
    float s = 0.f;
    for (int t = 0; t < nt; t++) s += p[t];
    g_rsum[idx] = s;
}

// ---------------- K4: normalize + 16x16 head-mix of probs, write g_P[i][j] fp16 ----------------
__global__ void __launch_bounds__(256) k_mixp(const float* __restrict__ Wpost)
{
    extern __shared__ float Es[];        // [16][32][33]
    __shared__ float Ws[HH][HH];
    __shared__ float invl[HH][32];

    int pidx = blockIdx.x;               // 0..2079 lower-tri pair over 64 tiles
    int b = blockIdx.y;
    int ti = (int)((sqrtf(8.f * pidx + 1.f) - 1.f) * 0.5f);
    while ((ti + 1) * (ti + 2) / 2 <= pidx) ti++;
    while (ti * (ti + 1) / 2 > pidx) ti--;
    int tj = pidx - ti * (ti + 1) / 2;
    int i0 = ti * 32, j0 = tj * 32;

    int tid = threadIdx.x;
    if (tid < HH * HH) Ws[tid >> 4][tid & 15] = Wpost[tid];
#pragma unroll
    for (int q = 0; q < 2; q++) {
        int idx = q * 256 + tid;         // 512 entries
        int ff = idx >> 5, r = idx & 31;
        invl[ff][r] = 1.0f / g_rsum[(size_t)(b * HH + ff) * NN + i0 + r];
    }
#pragma unroll
    for (int p = 0; p < 16; p++) {
        int idx = p * 256 + tid;         // 4096 x 8B loads
        int f = idx >> 8;
        int r = (idx >> 3) & 31;
        int c4 = idx & 7;
        uint2 uv = *(const uint2*)&g_S[((size_t)(b * HH + f) * NN + i0 + r) * NN + j0 + c4 * 4];
        float4 val = u2f4(uv);
        float* ep = &Es[f * 1056 + r * 33 + c4 * 4];
        ep[0] = val.x; ep[1] = val.y; ep[2] = val.z; ep[3] = val.w;
    }
    __syncthreads();

    int i  = tid >> 3;          // 0..31 (i within tile)
    int j4 = tid & 7;           // 4 consecutive j per thread
    float acc[16][4];
#pragma unroll
    for (int e = 0; e < 16; e++)
#pragma unroll
        for (int u = 0; u < 4; u++) acc[e][u] = 0.f;

#pragma unroll
    for (int f = 0; f < 16; f++) {
        float il = invl[f][i];
        float p0 = Es[f * 1056 + i * 33 + j4 * 4 + 0] * il;
        float p1 = Es[f * 1056 + i * 33 + j4 * 4 + 1] * il;
        float p2 = Es[f * 1056 + i * 33 + j4 * 4 + 2] * il;
        float p3 = Es[f * 1056 + i * 33 + j4 * 4 + 3] * il;
#pragma unroll
        for (int e = 0; e < 16; e++) {
            float w = Ws[e][f];
            acc[e][0] += w * p0; acc[e][1] += w * p1;
            acc[e][2] += w * p2; acc[e][3] += w * p3;
        }
    }
#pragma unroll
    for (int e = 0; e < 16; e++) {
        uint2 w = make_uint2(h2u(acc[e][0], acc[e][1]), h2u(acc[e][2], acc[e][3]));
        *(uint2*)&g_P[((size_t)(b * HH + e) * NN + i0 + i) * NN + j0 + j4 * 4] = w;
    }
}

// ---------------- K5: out = Pmix @ V, tensor cores (A = P[i][j], B = V via ldmatrix.trans) ----------------
__global__ void __launch_bounds__(256) k_pv(float* __restrict__ out)
{
    __shared__ __half Ps[128 * 40];
    __shared__ __half Vs[32 * 72];

    int bi = blockIdx.x;
    int ti = 15 - (bi & 15);       // heavy tiles first
    int bh = bi >> 4;
    int i0 = ti * 128;

    const __half* Pb = g_P  + (size_t)bh * NN * NN;
    const __half* vb = g_vh + (size_t)bh * NN * DD;

    int tid = threadIdx.x;
    int w = tid >> 5, l = tid & 31;
    int wm0 = (w >> 2) * 64;        // warp rows (i)
    int wn0 = (w & 3) * 16;         // warp cols (d)
    unsigned pbase = sm_addr(Ps), vbase = sm_addr(Vs);

    float acc[4][2][4];
#pragma unroll
    for (int mi = 0; mi < 4; mi++)
#pragma unroll
        for (int ni = 0; ni < 2; ni++)
#pragma unroll
            for (int u = 0; u < 4; u++) acc[mi][ni][u] = 0.f;

    int njt = (ti + 1) * 4;
    for (int jt = 0; jt < njt; jt++) {
        int j0 = jt * 32;
#pragma unroll
        for (int p = 0; p < 2; p++) {
            int idx = p * 256 + tid;        // 512 = 128 rows x 4 chunks
            int r = idx >> 2, c8 = idx & 3;
            *(uint4*)&Ps[r * 40 + c8 * 8] = *(const uint4*)&Pb[((size_t)(i0 + r)) * NN + j0 + c8 * 8];
        }
        {
            int r = tid >> 3, c8 = tid & 7; // 256 = 32 rows x 8 chunks
            *(uint4*)&Vs[r * 72 + c8 * 8] = *(const uint4*)&vb[((size_t)(j0 + r)) * DD + c8 * 8];
        }
        __syncthreads();

#pragma unroll
        for (int kk = 0; kk < 32; kk += 16) {
            unsigned a[4][4], b[2][2];
#pragma unroll
            for (int mi = 0; mi < 4; mi++)
                ldsm_x4(a[mi], pbase + ((wm0 + mi * 16 + (l & 15)) * 40 + kk + (l >> 4) * 8) * 2);
#pragma unroll
            for (int ni = 0; ni < 2; ni++)
                ldsm_x2t(b[ni], vbase + ((kk + (l & 15)) * 72 + wn0 + ni * 8) * 2);
#pragma unroll
            for (int mi = 0; mi < 4; mi++)
#pragma unroll
                for (int ni = 0; ni < 2; ni++)
                    mma16816(acc[mi][ni], a[mi], b[ni]);
        }
        __syncthreads();
    }

    int grp = l >> 2, qd = l & 3;
#pragma unroll
    for (int mi = 0; mi < 4; mi++)
#pragma unroll
        for (int h = 0; h < 2; h++) {
            int row = wm0 + mi * 16 + grp + h * 8;
#pragma unroll
            for (int ni = 0; ni < 2; ni++) {
                int col = wn0 + ni * 8 + qd * 2;
                float2 o = make_float2(acc[mi][ni][2 * h], acc[mi][ni][2 * h + 1]);
                *(float2*)&out[((size_t)bh * NN + i0 + row) * DD + col] = o;
            }
        }
}

// ---------------- launcher ----------------
extern "C" void kernel_launch(void* const* d_in, const int* in_sizes, int n_in,
                              void* d_out, int out_size)
{
    const float* q     = (const float*)d_in[0];
    const float* k     = (const float*)d_in[1];
    const float* v     = (const float*)d_in[2];
    const float* Wpre  = (const float*)d_in[3];
    const float* Wpost = (const float*)d_in[4];
    float* out = (float*)d_out;

    cudaFuncSetAttribute(k_mixp, cudaFuncAttributeMaxDynamicSharedMemorySize, 16 * 1056 * 4);

    // 1) head-mix with W_pre (fp16 out, original [n][d] layout), v->fp16
    k_mix<<<(BB * NN * DD) / 256, 256>>>(q, k, Wpre);
    k_vh<<<(BH * NN * DD) / 1024, 256>>>(v);

    // 1b) row norms of mixed q (fp16), per-head max norm of mixed k
    k_norms<<<dim3(NN / 256, BH), 256>>>();

    // 1c) zero strictly-upper 32-tiles inside diagonal 128-blocks of g_P
    k_zerop<<<BH * 16, 256>>>();

    // 2) scores via tensor cores + fused exp(s-c) + partial row sums
    k_qk<<<dim3(136, BH), 256>>>();

    // 2b) reduce partial row sums
    k_rsum<<<(BH * NN) / 256, 256>>>();

    // 3) normalize + head-mix probs with W_post -> g_P[i][j] fp16
    k_mixp<<<dim3(2080, BB), 256, 16 * 1056 * 4>>>(Wpost);

    // 4) PV via tensor cores
    k_pv<<<BH * 16, 256>>>(out);
}

// round 10
// speedup vs baseline: 3.1482x; 1.1019x over previous
#include <cuda_runtime.h>
#include <cuda_fp16.h>
#include <math.h>

#define BB 2
#define HH 16
#define NN 2048
#define DD 64
#define BH (BB*HH)
#define SCALE 0.03125f   // 1/(sqrt(16)*sqrt(64))

// ---------------- scratch (static device globals; no allocation) ----------------
__device__ __half g_qh[(size_t)BH*NN*DD];      // head-mixed q, fp16 [b,e,n,d]
__device__ __half g_kh[(size_t)BH*NN*DD];      // head-mixed k, fp16 [b,e,n,d]
__device__ __half g_vh[(size_t)BH*NN*DD];      // v, fp16 [b,h,n,d]
__device__ __half g_S [(size_t)BH*NN*NN];      // unnormalized exp(s - c), fp16 (256MB)
__device__ __half g_P [(size_t)BH*NN*NN];      // mixed probs [b,e,i,j], fp16 (256MB)
__device__ float  g_rsum[(size_t)BH*NN];       // softmax row sums
__device__ float  g_psum[(size_t)BH*NN*16];    // per-(row, j-tile) partial sums
__device__ float  g_qnorm[(size_t)BH*NN];      // ||q_mixed_i|| (of fp16 values)
__device__ float  g_kmax[BH];                  // max_j ||k_mixed_j|| per (b,h)
// g_kmax: zero-initialized at load; atomicMax over identical deterministic
// inputs is idempotent -> no per-launch reset needed (graph-capture safe).

// ---------------- helpers ----------------
__device__ __forceinline__ unsigned h2u(float a, float b) {
    __half2 h = __floats2half2_rn(a, b);
    return *(unsigned*)&h;
}
__device__ __forceinline__ float4 u2f4(uint2 u) {
    float2 f0 = __half22float2(*(__half2*)&u.x);
    float2 f1 = __half22float2(*(__half2*)&u.y);
    return make_float4(f0.x, f0.y, f1.x, f1.y);
}
__device__ __forceinline__ unsigned sm_addr(const void* p) {
    return (unsigned)__cvta_generic_to_shared(p);
}
__device__ __forceinline__ void ldsm_x4(unsigned* r, unsigned a) {
    asm volatile("ldmatrix.sync.aligned.m8n8.x4.shared.b16 {%0,%1,%2,%3}, [%4];\n"
        : "=r"(r[0]), "=r"(r[1]), "=r"(r[2]), "=r"(r[3]) : "r"(a));
}
__device__ __forceinline__ void ldsm_x2(unsigned* r, unsigned a) {
    asm volatile("ldmatrix.sync.aligned.m8n8.x2.shared.b16 {%0,%1}, [%2];\n"
        : "=r"(r[0]), "=r"(r[1]) : "r"(a));
}
__device__ __forceinline__ void ldsm_x2t(unsigned* r, unsigned a) {
    asm volatile("ldmatrix.sync.aligned.m8n8.x2.trans.shared.b16 {%0,%1}, [%2];\n"
        : "=r"(r[0]), "=r"(r[1]) : "r"(a));
}
__device__ __forceinline__ void mma16816(float* c, const unsigned* a, const unsigned* b) {
    asm volatile(
        "mma.sync.aligned.m16n8k16.row.col.f32.f16.f16.f32 "
        "{%0,%1,%2,%3}, {%4,%5,%6,%7}, {%8,%9}, {%0,%1,%2,%3};\n"
        : "+f"(c[0]), "+f"(c[1]), "+f"(c[2]), "+f"(c[3])
        : "r"(a[0]), "r"(a[1]), "r"(a[2]), "r"(a[3]), "r"(b[0]), "r"(b[1]));
}

// ---------------- K1: head-mix q,k with W_pre, fp16 out ----------------
__global__ void k_mix(const float* __restrict__ q, const float* __restrict__ k,
                      const float* __restrict__ Wpre)
{
    __shared__ float Ws[HH][HH];
    int tid = threadIdx.x;
    if (tid < HH * HH) Ws[tid >> 4][tid & 15] = Wpre[tid];
    __syncthreads();

    size_t idx = (size_t)blockIdx.x * 256 + tid;          // over B*N*D = 262144 sites
    int d = (int)(idx % DD);
    int n = (int)((idx / DD) % NN);
    int b = (int)(idx / ((size_t)NN * DD));
    size_t site = ((size_t)n) * DD + d;

    float xv[HH];
#pragma unroll
    for (int f = 0; f < HH; f++)
        xv[f] = q[((size_t)(b * HH + f) * NN) * DD + site];
#pragma unroll
    for (int e = 0; e < HH; e++) {
        float a = 0.f;
#pragma unroll
        for (int f = 0; f < HH; f++) a += Ws[e][f] * xv[f];
        g_qh[((size_t)(b * HH + e) * NN) * DD + site] = __float2half_rn(a);
    }
#pragma unroll
    for (int f = 0; f < HH; f++)
        xv[f] = k[((size_t)(b * HH + f) * NN) * DD + site];
#pragma unroll
    for (int e = 0; e < HH; e++) {
        float a = 0.f;
#pragma unroll
        for (int f = 0; f < HH; f++) a += Ws[e][f] * xv[f];
        g_kh[((size_t)(b * HH + e) * NN) * DD + site] = __float2half_rn(a);
    }
}

// ---------------- K1b: v -> fp16 ----------------
__global__ void k_vh(const float* __restrict__ v)
{
    size_t i = ((size_t)blockIdx.x * 256 + threadIdx.x) * 4;
    float4 f = *(const float4*)&v[i];
    *(uint2*)&g_vh[i] = make_uint2(h2u(f.x, f.y), h2u(f.z, f.w));
}

// ---------------- K1c: ||q_i|| per row (fp16 values), max ||k_j|| per head ----------------
__global__ void k_norms()
{
    int bh = blockIdx.y;
    int n  = blockIdx.x * 256 + threadIdx.x;
    const __half* qb = g_qh + ((size_t)bh * NN + n) * DD;
    const __half* kb = g_kh + ((size_t)bh * NN + n) * DD;
    float sq = 0.f, sk = 0.f;
#pragma unroll
    for (int d = 0; d < DD; d += 2) {
        float2 a = __half22float2(*(const __half2*)&qb[d]);
        float2 b = __half22float2(*(const __half2*)&kb[d]);
        sq += a.x * a.x + a.y * a.y;
        sk += b.x * b.x + b.y * b.y;
    }
    g_qnorm[(size_t)bh * NN + n] = sqrtf(sq);
    float kn = sqrtf(sk);

    __shared__ float red[256];
    int tid = threadIdx.x;
    red[tid] = kn;
    __syncthreads();
    for (int s = 128; s > 0; s >>= 1) {
        if (tid < s) red[tid] = fmaxf(red[tid], red[tid + s]);
        __syncthreads();
    }
    if (tid == 0)
        atomicMax((int*)&g_kmax[bh], __float_as_int(red[0]));  // all > 0; idempotent
}

// ---------------- K1d: zero strictly-upper 32-tiles inside diagonal 128-blocks of g_P ----------------
__global__ void k_zerop()
{
    int be  = blockIdx.x >> 4;          // 0..31 (b*HH+e)
    int blk = blockIdx.x & 15;          // diag 128-block
    int r = threadIdx.x >> 3, c = threadIdx.x & 7;
    const int pa[6] = {0,0,0,1,1,2}, pb[6] = {1,2,3,2,3,3};
#pragma unroll
    for (int u = 0; u < 6; u++) {
        size_t off = ((size_t)be * NN + blk * 128 + pa[u] * 32 + r) * NN
                   + blk * 128 + pb[u] * 32 + c * 4;
        *(uint2*)&g_P[off] = make_uint2(0u, 0u);
    }
}

// ---- K2: lower-tri 128x128x64 tensor-core GEMM + fused exp(s-c) + partial sums,
//      coalesced S store via smem staging (reuses Q/K smem) ----
__global__ void __launch_bounds__(256) k_qk()
{
    __shared__ __half QK[2 * 128 * 72];        // Qs | Ks, reused as St staging
    __shared__ float  psumS[128][4];
    __half* Qs = QK;
    __half* Ks = QK + 128 * 72;
    __half* St = QK;                           // 128 x 136 staging (<= 18432 halves x2)

    int pidx = blockIdx.x;       // 0..135 lower-tri pair (ti>=tj)
    int ti = (int)((sqrtf(8.f * pidx + 1.f) - 1.f) * 0.5f);
    while ((ti + 1) * (ti + 2) / 2 <= pidx) ti++;
    while (ti * (ti + 1) / 2 > pidx) ti--;
    int tj = pidx - ti * (ti + 1) / 2;
    int bh = blockIdx.y;

    const __half* qb = g_qh + ((size_t)bh * NN + ti * 128) * DD;
    const __half* kb = g_kh + ((size_t)bh * NN + tj * 128) * DD;

    int tid = threadIdx.x;
#pragma unroll
    for (int p = 0; p < 4; p++) {
        int idx = p * 256 + tid;            // 1024 = 128 rows x 8 chunks
        int r = idx >> 3, c8 = idx & 7;
        *(uint4*)&Qs[r * 72 + c8 * 8] = *(const uint4*)&qb[r * 64 + c8 * 8];
        *(uint4*)&Ks[r * 72 + c8 * 8] = *(const uint4*)&kb[r * 64 + c8 * 8];
    }
    __syncthreads();

    int w = tid >> 5, l = tid & 31;
    int wm0 = (w >> 2) * 64;                // warp rows
    int wn0 = (w & 3) * 32;                 // warp cols
    unsigned qbase = sm_addr(Qs), kbase = sm_addr(Ks);

    float acc[4][4][4];
#pragma unroll
    for (int mi = 0; mi < 4; mi++)
#pragma unroll
        for (int ni = 0; ni < 4; ni++)
#pragma unroll
            for (int u = 0; u < 4; u++) acc[mi][ni][u] = 0.f;

#pragma unroll
    for (int kk = 0; kk < 64; kk += 16) {
        unsigned a[4][4], b[4][2];
#pragma unroll
        for (int mi = 0; mi < 4; mi++)
            ldsm_x4(a[mi], qbase + ((wm0 + mi * 16 + (l & 15)) * 72 + kk + (l >> 4) * 8) * 2);
#pragma unroll
        for (int ni = 0; ni < 4; ni++)
            ldsm_x2(b[ni], kbase + ((wn0 + ni * 8 + (l & 7)) * 72 + kk + ((l >> 3) & 1) * 8) * 2);
#pragma unroll
        for (int mi = 0; mi < 4; mi++)
#pragma unroll
            for (int ni = 0; ni < 4; ni++)
                mma16816(acc[mi][ni], a[mi], b[ni]);
    }
    __syncthreads();               // Qs/Ks dead -> safe to reuse as St

    // Epilogue: exp(s - c_row), c_row = SCALE*||q_i||*kmax (true upper bound).
    float kmaxv = g_kmax[bh];
    bool isdiag = (ti == tj);
    int grp = l >> 2, qd = l & 3;

#pragma unroll
    for (int mi = 0; mi < 4; mi++) {
#pragma unroll
        for (int h = 0; h < 2; h++) {
            int row = wm0 + mi * 16 + grp + h * 8;          // local row in tile
            float cb = SCALE * g_qnorm[(size_t)bh * NN + ti * 128 + row] * kmaxv;
            float rsum = 0.f;
#pragma unroll
            for (int ni = 0; ni < 4; ni++) {
                int col = wn0 + ni * 8 + qd * 2;            // local col
                float e0 = __expf(acc[mi][ni][2 * h]     * SCALE - cb);
                float e1 = __expf(acc[mi][ni][2 * h + 1] * SCALE - cb);
                if (isdiag && col     > row) e0 = 0.f;
                if (isdiag && col + 1 > row) e1 = 0.f;
                rsum += e0 + e1;
                *(unsigned*)&St[row * 136 + col] = h2u(e0, e1);   // conflict-free (stride 136)
            }
            rsum += __shfl_xor_sync(0xffffffff, rsum, 1);
            rsum += __shfl_xor_sync(0xffffffff, rsum, 2);
            if (qd == 0) psumS[row][w & 3] = rsum;
        }
    }
    __syncthreads();

    // Coalesced flush: 128 rows x 128 halves as uint4 (256B per 16 threads)
    __half* Sb = g_S + (size_t)bh * NN * NN;
#pragma unroll
    for (int p = 0; p < 8; p++) {
        int idx = p * 256 + tid;           // 2048 = 128 rows x 16 chunks
        int r = idx >> 4, c8 = idx & 15;
        *(uint4*)&Sb[(size_t)(ti * 128 + r) * NN + tj * 128 + c8 * 8] =
            *(uint4*)&St[r * 136 + c8 * 8];
    }
    if (tid < 128) {
        float s = psumS[tid][0] + psumS[tid][1] + psumS[tid][2] + psumS[tid][3];
        g_psum[((size_t)bh * NN + ti * 128 + tid) * 16 + tj] = s;
    }
}

// ---------------- K3: reduce partial row sums ----------------
__global__ void k_rsum()
{
    size_t idx = (size_t)blockIdx.x * 256 + threadIdx.x;   // BH*NN rows
    int i = (int)(idx & (NN - 1));
    int nt = (i >> 7) + 1;
    const float* p = g_psum + idx * 16;
    float s = 0.f;
    for (int t = 0; t < nt; t++) s += p[t];
    g_rsum[idx] = s;
}

// ---- K4: normalize + head-mix probs via tensor cores (A=W_post, k-dim=f), coalesced I/O ----
__global__ void __launch_bounds__(256) k_mixp(const float* __restrict__ Wpost)
{
    extern __shared__ char smraw[];
    float*  invl = (float*)smraw;                        // 16*32 floats   (2048B)
    __half* Wh   = (__half*)(smraw + 2048);              // 16 x 24 halves (768B, pad 1024)
    __half* Bs   = (__half*)(smraw + 3072);              // 16 x 1032 halves (33024B) [f][site]
    __half* Os   = (__half*)(smraw + 3072 + 33024);      // 16 x 1032 halves          [e][site]

    int pidx = blockIdx.x;               // 0..2079 lower-tri pair over 64 tiles
    int b = blockIdx.y;
    int ti = (int)((sqrtf(8.f * pidx + 1.f) - 1.f) * 0.5f);
    while ((ti + 1) * (ti + 2) / 2 <= pidx) ti++;
    while (ti * (ti + 1) / 2 > pidx) ti--;
    int tj = pidx - ti * (ti + 1) / 2;
    int i0 = ti * 32, j0 = tj * 32;

    int tid = threadIdx.x;
    Wh[(tid >> 4) * 24 + (tid & 15)] = __float2half_rn(Wpost[tid]);
#pragma unroll
    for (int q = 0; q < 2; q++) {
        int idx = q * 256 + tid;         // 512 entries
        int ff = idx >> 5, r = idx & 31;
        invl[ff * 32 + r] = 1.0f / g_rsum[(size_t)(b * HH + ff) * NN + i0 + r];
    }
    __syncthreads();

    // Stage normalized Sn as fp16 [f][site], site = i*32 + j
#pragma unroll
    for (int p = 0; p < 16; p++) {
        int idx = p * 256 + tid;         // 4096 x 8B loads
        int f = idx >> 8;
        int r = (idx >> 3) & 31;
        int c4 = idx & 7;
        uint2 uv = *(const uint2*)&g_S[((size_t)(b * HH + f) * NN + i0 + r) * NN + j0 + c4 * 4];
        float4 val = u2f4(uv);
        float il = invl[f * 32 + r];
        *(uint2*)&Bs[f * 1032 + r * 32 + c4 * 4] =
            make_uint2(h2u(val.x * il, val.y * il), h2u(val.z * il, val.w * il));
    }
    __syncthreads();

    // Mix: one mma per 8-site group covers all 16 e (A = W 16x16, B = Sn 16f x 8sites)
    int w = tid >> 5, l = tid & 31;
    int grp = l >> 2, qd = l & 3;
    unsigned a[4];
    ldsm_x4(a, sm_addr(Wh) + ((l & 15) * 24 + (l >> 4) * 8) * 2);
#pragma unroll
    for (int t = 0; t < 16; t++) {
        int s0 = (w * 16 + t) * 8;       // 128 groups of 8 sites
        unsigned bfr[2];
        ldsm_x2t(bfr, sm_addr(Bs) + ((l & 15) * 1032 + s0) * 2);
        float c[4] = {0.f, 0.f, 0.f, 0.f};
        mma16816(c, a, bfr);
        *(unsigned*)&Os[grp * 1032 + s0 + qd * 2]       = h2u(c[0], c[1]);
        *(unsigned*)&Os[(grp + 8) * 1032 + s0 + qd * 2] = h2u(c[2], c[3]);
    }
    __syncthreads();

    // Coalesced flush of P: 16e x 32i x 32j
#pragma unroll
    for (int p = 0; p < 8; p++) {
        int idx = p * 256 + tid;         // 2048 = 16e x 32i x 4 chunks
        int e = idx >> 7;
        int i = (idx >> 2) & 31;
        int c8 = idx & 3;
        *(uint4*)&g_P[((size_t)(b * HH + e) * NN + i0 + i) * NN + j0 + c8 * 8] =
            *(uint4*)&Os[e * 1032 + i * 32 + c8 * 8];
    }
}

// ---------------- K5: out = Pmix @ V, tensor cores, j-tile 64 ----------------
__global__ void __launch_bounds__(256) k_pv(float* __restrict__ out)
{
    __shared__ __half Ps[128 * 72];
    __shared__ __half Vs[64 * 72];

    int bi = blockIdx.x;
    int ti = 15 - (bi & 15);       // heavy tiles first
    int bh = bi >> 4;
    int i0 = ti * 128;

    const __half* Pb = g_P  + (size_t)bh * NN * NN;
    const __half* vb = g_vh + (size_t)bh * NN * DD;

    int tid = threadIdx.x;
    int w = tid >> 5, l = tid & 31;
    int wm0 = (w >> 2) * 64;        // warp rows (i)
    int wn0 = (w & 3) * 16;         // warp cols (d)
    unsigned pbase = sm_addr(Ps), vbase = sm_addr(Vs);

    float acc[4][2][4];
#pragma unroll
    for (int mi = 0; mi < 4; mi++)
#pragma unroll
        for (int ni = 0; ni < 2; ni++)
#pragma unroll
            for (int u = 0; u < 4; u++) acc[mi][ni][u] = 0.f;

    int njt = (ti + 1) * 2;
    for (int jt = 0; jt < njt; jt++) {
        int j0 = jt * 64;
#pragma unroll
        for (int p = 0; p < 4; p++) {
            int idx = p * 256 + tid;        // 1024 = 128 rows x 8 chunks
            int r = idx >> 3, c8 = idx & 7;
            *(uint4*)&Ps[r * 72 + c8 * 8] = *(const uint4*)&Pb[((size_t)(i0 + r)) * NN + j0 + c8 * 8];
        }
#pragma unroll
        for (int p = 0; p < 2; p++) {
            int idx = p * 256 + tid;        // 512 = 64 rows x 8 chunks
            int r = idx >> 3, c8 = idx & 7;
            *(uint4*)&Vs[r * 72 + c8 * 8] = *(const uint4*)&vb[((size_t)(j0 + r)) * DD + c8 * 8];
        }
        __syncthreads();

#pragma unroll
        for (int kk = 0; kk < 64; kk += 16) {
            unsigned a[4][4], b[2][2];
#pragma unroll
            for (int mi = 0; mi < 4; mi++)
                ldsm_x4(a[mi], pbase + ((wm0 + mi * 16 + (l & 15)) * 72 + kk + (l >> 4) * 8) * 2);
#pragma unroll
            for (int ni = 0; ni < 2; ni++)
                ldsm_x2t(b[ni], vbase + ((kk + (l & 15)) * 72 + wn0 + ni * 8) * 2);
#pragma unroll
            for (int mi = 0; mi < 4; mi++)
#pragma unroll
                for (int ni = 0; ni < 2; ni++)
                    mma16816(acc[mi][ni], a[mi], b[ni]);
        }
        __syncthreads();
    }

    int grp = l >> 2, qd = l & 3;
#pragma unroll
    for (int mi = 0; mi < 4; mi++)
#pragma unroll
        for (int h = 0; h < 2; h++) {
            int row = wm0 + mi * 16 + grp + h * 8;
#pragma unroll
            for (int ni = 0; ni < 2; ni++) {
                int col = wn0 + ni * 8 + qd * 2;
                float2 o = make_float2(acc[mi][ni][2 * h], acc[mi][ni][2 * h + 1]);
                *(float2*)&out[((size_t)bh * NN + i0 + row) * DD + col] = o;
            }
        }
}

// ---------------- launcher ----------------
extern "C" void kernel_launch(void* const* d_in, const int* in_sizes, int n_in,
                              void* d_out, int out_size)
{
    const float* q     = (const float*)d_in[0];
    const float* k     = (const float*)d_in[1];
    const float* v     = (const float*)d_in[2];
    const float* Wpre  = (const float*)d_in[3];
    const float* Wpost = (const float*)d_in[4];
    float* out = (float*)d_out;

    cudaFuncSetAttribute(k_mixp, cudaFuncAttributeMaxDynamicSharedMemorySize, 70 * 1024);

    // 1) head-mix with W_pre (fp16 out), v->fp16
    k_mix<<<(BB * NN * DD) / 256, 256>>>(q, k, Wpre);
    k_vh<<<(BH * NN * DD) / 1024, 256>>>(v);

    // 1b) row norms of mixed q (fp16), per-head max norm of mixed k
    k_norms<<<dim3(NN / 256, BH), 256>>>();

    // 1c) zero strictly-upper 32-tiles inside diagonal 128-blocks of g_P
    k_zerop<<<BH * 16, 256>>>();

    // 2) scores via tensor cores + fused exp(s-c) + partial row sums (coalesced store)
    k_qk<<<dim3(136, BH), 256>>>();

    // 2b) reduce partial row sums
    k_rsum<<<(BH * NN) / 256, 256>>>();

    // 3) normalize + head-mix probs via tensor cores -> g_P fp16
    k_mixp<<<dim3(2080, BB), 256, 70 * 1024>>>(Wpost);

    // 4) PV via tensor cores, j-tile 64
    k_pv<<<BH * 16, 256>>>(out);
}

// round 12
// speedup vs baseline: 3.4530x; 1.0968x over previous
#include <cuda_runtime.h>
#include <cuda_fp16.h>
#include <math.h>

#define BB 2
#define HH 16
#define NN 2048
#define DD 64
#define BH (BB*HH)
#define SCALE 0.03125f   // 1/(sqrt(16)*sqrt(64))

// ---------------- scratch (static device globals; no allocation) ----------------
__device__ __half g_qh[(size_t)BH*NN*DD];      // head-mixed q, fp16 [b,e,n,d]
__device__ __half g_kh[(size_t)BH*NN*DD];      // head-mixed k, fp16 [b,e,n,d]
__device__ __half g_vh[(size_t)BH*NN*DD];      // v, fp16 [b,h,n,d]
__device__ __half g_S [(size_t)BH*NN*NN];      // unnormalized exp(s - c), fp16 (256MB)
__device__ __half g_P [(size_t)BH*NN*NN];      // mixed probs [b,e,i,j], fp16 (256MB)
__device__ float  g_rsum[(size_t)BH*NN];       // softmax row sums
__device__ float  g_psum[(size_t)BH*NN*16];    // per-(row, j-tile) partial sums
__device__ float  g_qnorm[(size_t)BH*NN];      // ||q_mixed_i|| (of fp16 values)
__device__ float  g_kmax[BH];                  // max_j ||k_mixed_j|| per (b,h)
// g_kmax: zero-initialized at load; atomicMax over identical deterministic
// inputs is idempotent -> no per-launch reset needed (graph-capture safe).

// ---------------- helpers ----------------
__device__ __forceinline__ unsigned h2u(float a, float b) {
    __half2 h = __floats2half2_rn(a, b);
    return *(unsigned*)&h;
}
__device__ __forceinline__ float4 u2f4(uint2 u) {
    float2 f0 = __half22float2(*(__half2*)&u.x);
    float2 f1 = __half22float2(*(__half2*)&u.y);
    return make_float4(f0.x, f0.y, f1.x, f1.y);
}
__device__ __forceinline__ unsigned sm_addr(const void* p) {
    return (unsigned)__cvta_generic_to_shared(p);
}
__device__ __forceinline__ void ldsm_x4(unsigned* r, unsigned a) {
    asm volatile("ldmatrix.sync.aligned.m8n8.x4.shared.b16 {%0,%1,%2,%3}, [%4];\n"
        : "=r"(r[0]), "=r"(r[1]), "=r"(r[2]), "=r"(r[3]) : "r"(a));
}
__device__ __forceinline__ void ldsm_x2(unsigned* r, unsigned a) {
    asm volatile("ldmatrix.sync.aligned.m8n8.x2.shared.b16 {%0,%1}, [%2];\n"
        : "=r"(r[0]), "=r"(r[1]) : "r"(a));
}
__device__ __forceinline__ void ldsm_x2t(unsigned* r, unsigned a) {
    asm volatile("ldmatrix.sync.aligned.m8n8.x2.trans.shared.b16 {%0,%1}, [%2];\n"
        : "=r"(r[0]), "=r"(r[1]) : "r"(a));
}
__device__ __forceinline__ void mma16816(float* c, const unsigned* a, const unsigned* b) {
    asm volatile(
        "mma.sync.aligned.m16n8k16.row.col.f32.f16.f16.f32 "
        "{%0,%1,%2,%3}, {%4,%5,%6,%7}, {%8,%9}, {%0,%1,%2,%3};\n"
        : "+f"(c[0]), "+f"(c[1]), "+f"(c[2]), "+f"(c[3])
        : "r"(a[0]), "r"(a[1]), "r"(a[2]), "r"(a[3]), "r"(b[0]), "r"(b[1]));
}
__device__ __forceinline__ void cp16(unsigned s, const void* g) {
    asm volatile("cp.async.cg.shared.global [%0], [%1], 16;\n" :: "r"(s), "l"(g));
}
__device__ __forceinline__ void cp_commit() {
    asm volatile("cp.async.commit_group;\n");
}

// ---- K1: fused prep: head-mix q,k (fp16 out) + v->fp16 + q-norms + k-max ----
// block = 256 threads = 16 rows x 16 d-quads; grid = (NN/16, BB)
__global__ void __launch_bounds__(256) k_prep(const float* __restrict__ q,
                                              const float* __restrict__ k,
                                              const float* __restrict__ v,
                                              const float* __restrict__ Wpre)
{
    __shared__ float Ws[HH][HH];
    __shared__ float snorm[HH][16];

    int tid = threadIdx.x;
    Ws[tid >> 4][tid & 15] = Wpre[tid];
    __syncthreads();

    int b  = blockIdx.y;
    int n0 = blockIdx.x * 16;
    int r  = tid >> 4;               // row 0..15
    int dq = tid & 15;               // d-quad 0..15
    int n  = n0 + r;
    size_t base = ((size_t)b * HH * NN + n) * DD + dq * 4;   // + f*NN*DD per head
    const size_t hs = (size_t)NN * DD;

    float acc4[HH][4];
    float sq[HH];

    // ----- q: mix, store fp16, norm of fp16 values -----
#pragma unroll
    for (int e = 0; e < HH; e++) { acc4[e][0] = acc4[e][1] = acc4[e][2] = acc4[e][3] = 0.f; }
#pragma unroll
    for (int f = 0; f < HH; f++) {
        float4 x = *(const float4*)&q[base + f * hs];
#pragma unroll
        for (int e = 0; e < HH; e++) {
            float w = Ws[e][f];
            acc4[e][0] += w * x.x; acc4[e][1] += w * x.y;
            acc4[e][2] += w * x.z; acc4[e][3] += w * x.w;
        }
    }
#pragma unroll
    for (int e = 0; e < HH; e++) {
        uint2 hv = make_uint2(h2u(acc4[e][0], acc4[e][1]), h2u(acc4[e][2], acc4[e][3]));
        *(uint2*)&g_qh[base + e * hs] = hv;
        float4 fb = u2f4(hv);                       // fp16-rounded values
        sq[e] = fb.x * fb.x + fb.y * fb.y + fb.z * fb.z + fb.w * fb.w;
    }
#pragma unroll
    for (int e = 0; e < HH; e++) {
        float s = sq[e];
        s += __shfl_xor_sync(0xffffffff, s, 1);
        s += __shfl_xor_sync(0xffffffff, s, 2);
        s += __shfl_xor_sync(0xffffffff, s, 4);
        s += __shfl_xor_sync(0xffffffff, s, 8);
        if (dq == 0) snorm[e][r] = s;
    }
    __syncthreads();
    g_qnorm[(size_t)(b * HH + (tid >> 4)) * NN + n0 + (tid & 15)] =
        sqrtf(snorm[tid >> 4][tid & 15]);
    __syncthreads();                                 // before snorm reuse

    // ----- k: mix, store fp16, per-head max norm -----
#pragma unroll
    for (int e = 0; e < HH; e++) { acc4[e][0] = acc4[e][1] = acc4[e][2] = acc4[e][3] = 0.f; }
#pragma unroll
    for (int f = 0; f < HH; f++) {
        float4 x = *(const float4*)&k[base + f * hs];
#pragma unroll
        for (int e = 0; e < HH; e++) {
            float w = Ws[e][f];
            acc4[e][0] += w * x.x; acc4[e][1] += w * x.y;
            acc4[e][2] += w * x.z; acc4[e][3] += w * x.w;
        }
    }
#pragma unroll
    for (int e = 0; e < HH; e++) {
        uint2 hv = make_uint2(h2u(acc4[e][0], acc4[e][1]), h2u(acc4[e][2], acc4[e][3]));
        *(uint2*)&g_kh[base + e * hs] = hv;
        float4 fb = u2f4(hv);
        sq[e] = fb.x * fb.x + fb.y * fb.y + fb.z * fb.z + fb.w * fb.w;
    }
#pragma unroll
    for (int e = 0; e < HH; e++) {
        float s = sq[e];
        s += __shfl_xor_sync(0xffffffff, s, 1);
        s += __shfl_xor_sync(0xffffffff, s, 2);
        s += __shfl_xor_sync(0xffffffff, s, 4);
        s += __shfl_xor_sync(0xffffffff, s, 8);
        if (dq == 0) snorm[e][r] = s;
    }
    __syncthreads();
    {
        float s2 = snorm[tid >> 4][tid & 15];        // (e = tid>>4, row = tid&15)
        s2 = fmaxf(s2, __shfl_xor_sync(0xffffffff, s2, 1));
        s2 = fmaxf(s2, __shfl_xor_sync(0xffffffff, s2, 2));
        s2 = fmaxf(s2, __shfl_xor_sync(0xffffffff, s2, 4));
        s2 = fmaxf(s2, __shfl_xor_sync(0xffffffff, s2, 8));
        if ((tid & 15) == 0)
            atomicMax((int*)&g_kmax[b * HH + (tid >> 4)], __float_as_int(sqrtf(s2)));
    }

    // ----- v -> fp16 (no mixing) -----
#pragma unroll
    for (int f = 0; f < HH; f++) {
        float4 x = *(const float4*)&v[base + f * hs];
        *(uint2*)&g_vh[base + f * hs] = make_uint2(h2u(x.x, x.y), h2u(x.z, x.w));
    }
}

// ---------------- K1d: zero strictly-upper 32-tiles inside diagonal 128-blocks of g_P ----------------
__global__ void k_zerop()
{
    int be  = blockIdx.x >> 4;          // 0..31 (b*HH+e)
    int blk = blockIdx.x & 15;          // diag 128-block
    int r = threadIdx.x >> 3, c = threadIdx.x & 7;
    const int pa[6] = {0,0,0,1,1,2}, pb[6] = {1,2,3,2,3,3};
#pragma unroll
    for (int u = 0; u < 6; u++) {
        size_t off = ((size_t)be * NN + blk * 128 + pa[u] * 32 + r) * NN
                   + blk * 128 + pb[u] * 32 + c * 4;
        *(uint2*)&g_P[off] = make_uint2(0u, 0u);
    }
}

// ---- K2: lower-tri 128x128x64 tensor-core GEMM + fused exp(s-c) + partial sums,
//      coalesced S store via smem staging (reuses Q/K smem) ----
__global__ void __launch_bounds__(256) k_qk()
{
    __shared__ __half QK[2 * 128 * 72];        // Qs | Ks, reused as St staging
    __shared__ float  psumS[128][4];
    __half* Qs = QK;
    __half* Ks = QK + 128 * 72;
    __half* St = QK;                           // 128 x 136 staging

    int pidx = blockIdx.x;       // 0..135 lower-tri pair (ti>=tj)
    int ti = (int)((sqrtf(8.f * pidx + 1.f) - 1.f) * 0.5f);
    while ((ti + 1) * (ti + 2) / 2 <= pidx) ti++;
    while (ti * (ti + 1) / 2 > pidx) ti--;
    int tj = pidx - ti * (ti + 1) / 2;
    int bh = blockIdx.y;

    const __half* qb = g_qh + ((size_t)bh * NN + ti * 128) * DD;
    const __half* kb = g_kh + ((size_t)bh * NN + tj * 128) * DD;

    int tid = threadIdx.x;
#pragma unroll
    for (int p = 0; p < 4; p++) {
        int idx = p * 256 + tid;            // 1024 = 128 rows x 8 chunks
        int r = idx >> 3, c8 = idx & 7;
        *(uint4*)&Qs[r * 72 + c8 * 8] = *(const uint4*)&qb[r * 64 + c8 * 8];
        *(uint4*)&Ks[r * 72 + c8 * 8] = *(const uint4*)&kb[r * 64 + c8 * 8];
    }
    __syncthreads();

    int w = tid >> 5, l = tid & 31;
    int wm0 = (w >> 2) * 64;                // warp rows
    int wn0 = (w & 3) * 32;                 // warp cols
    unsigned qbase = sm_addr(Qs), kbase = sm_addr(Ks);

    float acc[4][4][4];
#pragma unroll
    for (int mi = 0; mi < 4; mi++)
#pragma unroll
        for (int ni = 0; ni < 4; ni++)
#pragma unroll
            for (int u = 0; u < 4; u++) acc[mi][ni][u] = 0.f;

#pragma unroll
    for (int kk = 0; kk < 64; kk += 16) {
        unsigned a[4][4], b[4][2];
#pragma unroll
        for (int mi = 0; mi < 4; mi++)
            ldsm_x4(a[mi], qbase + ((wm0 + mi * 16 + (l & 15)) * 72 + kk + (l >> 4) * 8) * 2);
#pragma unroll
        for (int ni = 0; ni < 4; ni++)
            ldsm_x2(b[ni], kbase + ((wn0 + ni * 8 + (l & 7)) * 72 + kk + ((l >> 3) & 1) * 8) * 2);
#pragma unroll
        for (int mi = 0; mi < 4; mi++)
#pragma unroll
            for (int ni = 0; ni < 4; ni++)
                mma16816(acc[mi][ni], a[mi], b[ni]);
    }
    __syncthreads();               // Qs/Ks dead -> safe to reuse as St

    float kmaxv = g_kmax[bh];
    bool isdiag = (ti == tj);
    int grp = l >> 2, qd = l & 3;

#pragma unroll
    for (int mi = 0; mi < 4; mi++) {
#pragma unroll
        for (int h = 0; h < 2; h++) {
            int row = wm0 + mi * 16 + grp + h * 8;
            float cb = SCALE * g_qnorm[(size_t)bh * NN + ti * 128 + row] * kmaxv;
            float rsum = 0.f;
#pragma unroll
            for (int ni = 0; ni < 4; ni++) {
                int col = wn0 + ni * 8 + qd * 2;
                float e0 = __expf(acc[mi][ni][2 * h]     * SCALE - cb);
                float e1 = __expf(acc[mi][ni][2 * h + 1] * SCALE - cb);
                if (isdiag && col     > row) e0 = 0.f;
                if (isdiag && col + 1 > row) e1 = 0.f;
                rsum += e0 + e1;
                *(unsigned*)&St[row * 136 + col] = h2u(e0, e1);
            }
            rsum += __shfl_xor_sync(0xffffffff, rsum, 1);
            rsum += __shfl_xor_sync(0xffffffff, rsum, 2);
            if (qd == 0) psumS[row][w & 3] = rsum;
        }
    }
    __syncthreads();

    __half* Sb = g_S + (size_t)bh * NN * NN;
#pragma unroll
    for (int p = 0; p < 8; p++) {
        int idx = p * 256 + tid;           // 2048 = 128 rows x 16 chunks
        int r = idx >> 4, c8 = idx & 15;
        *(uint4*)&Sb[(size_t)(ti * 128 + r) * NN + tj * 128 + c8 * 8] =
            *(uint4*)&St[r * 136 + c8 * 8];
    }
    if (tid < 128) {
        float s = psumS[tid][0] + psumS[tid][1] + psumS[tid][2] + psumS[tid][3];
        g_psum[((size_t)bh * NN + ti * 128 + tid) * 16 + tj] = s;
    }
}

// ---------------- K3: reduce partial row sums ----------------
__global__ void k_rsum()
{
    size_t idx = (size_t)blockIdx.x * 256 + threadIdx.x;   // BH*NN rows
    int i = (int)(idx & (NN - 1));
    int nt = (i >> 7) + 1;
    const float* p = g_psum + idx * 16;
    float s = 0.f;
    for (int t = 0; t < nt; t++) s += p[t];
    g_rsum[idx] = s;
}

// ---- K4: normalize + head-mix probs via tensor cores (A=W_post, k-dim=f), coalesced I/O ----
__global__ void __launch_bounds__(256) k_mixp(const float* __restrict__ Wpost)
{
    extern __shared__ char smraw[];
    float*  invl = (float*)smraw;                        // 16*32 floats   (2048B)
    __half* Wh   = (__half*)(smraw + 2048);              // 16 x 24 halves (pad 1024)
    __half* Bs   = (__half*)(smraw + 3072);              // 16 x 1032 halves [f][site]
    __half* Os   = (__half*)(smraw + 3072 + 33024);      // 16 x 1032 halves [e][site]

    int pidx = blockIdx.x;               // 0..2079 lower-tri pair over 64 tiles
    int b = blockIdx.y;
    int ti = (int)((sqrtf(8.f * pidx + 1.f) - 1.f) * 0.5f);
    while ((ti + 1) * (ti + 2) / 2 <= pidx) ti++;
    while (ti * (ti + 1) / 2 > pidx) ti--;
    int tj = pidx - ti * (ti + 1) / 2;
    int i0 = ti * 32, j0 = tj * 32;

    int tid = threadIdx.x;
    Wh[(tid >> 4) * 24 + (tid & 15)] = __float2half_rn(Wpost[tid]);
#pragma unroll
    for (int q = 0; q < 2; q++) {
        int idx = q * 256 + tid;
        int ff = idx >> 5, r = idx & 31;
        invl[ff * 32 + r] = 1.0f / g_rsum[(size_t)(b * HH + ff) * NN + i0 + r];
    }
    __syncthreads();

#pragma unroll
    for (int p = 0; p < 16; p++) {
        int idx = p * 256 + tid;
        int f = idx >> 8;
        int r = (idx >> 3) & 31;
        int c4 = idx & 7;
        uint2 uv = *(const uint2*)&g_S[((size_t)(b * HH + f) * NN + i0 + r) * NN + j0 + c4 * 4];
        float4 val = u2f4(uv);
        float il = invl[f * 32 + r];
        *(uint2*)&Bs[f * 1032 + r * 32 + c4 * 4] =
            make_uint2(h2u(val.x * il, val.y * il), h2u(val.z * il, val.w * il));
    }
    __syncthreads();

    int w = tid >> 5, l = tid & 31;
    int grp = l >> 2, qd = l & 3;
    unsigned a[4];
    ldsm_x4(a, sm_addr(Wh) + ((l & 15) * 24 + (l >> 4) * 8) * 2);
#pragma unroll
    for (int t = 0; t < 16; t++) {
        int s0 = (w * 16 + t) * 8;
        unsigned bfr[2];
        ldsm_x2t(bfr, sm_addr(Bs) + ((l & 15) * 1032 + s0) * 2);
        float c[4] = {0.f, 0.f, 0.f, 0.f};
        mma16816(c, a, bfr);
        *(unsigned*)&Os[grp * 1032 + s0 + qd * 2]       = h2u(c[0], c[1]);
        *(unsigned*)&Os[(grp + 8) * 1032 + s0 + qd * 2] = h2u(c[2], c[3]);
    }
    __syncthreads();

#pragma unroll
    for (int p = 0; p < 8; p++) {
        int idx = p * 256 + tid;
        int e = idx >> 7;
        int i = (idx >> 2) & 31;
        int c8 = idx & 3;
        *(uint4*)&g_P[((size_t)(b * HH + e) * NN + i0 + i) * NN + j0 + c8 * 8] =
            *(uint4*)&Os[e * 1032 + i * 32 + c8 * 8];
    }
}

// ---- K5: out = Pmix @ V, tensor cores, j-tile 64, cp.async double-buffered ----
__global__ void __launch_bounds__(256) k_pv(float* __restrict__ out)
{
    extern __shared__ __half dsm[];
    __half* PsA[2] = { dsm,          dsm + 9216  };   // 128 x 72 each
    __half* VsA[2] = { dsm + 18432,  dsm + 23040 };   // 64 x 72 each

    int bi = blockIdx.x;
    int ti = 15 - (bi & 15);       // heavy tiles first
    int bh = bi >> 4;
    int i0 = ti * 128;

    const __half* Pb = g_P  + (size_t)bh * NN * NN;
    const __half* vb = g_vh + (size_t)bh * NN * DD;

    int tid = threadIdx.x;
    int w = tid >> 5, l = tid & 31;
    int wm0 = (w >> 2) * 64;        // warp rows (i)
    int wn0 = (w & 3) * 16;         // warp cols (d)

    float acc[4][2][4];
#pragma unroll
    for (int mi = 0; mi < 4; mi++)
#pragma unroll
        for (int ni = 0; ni < 2; ni++)
#pragma unroll
            for (int u = 0; u < 4; u++) acc[mi][ni][u] = 0.f;

    int njt = (ti + 1) * 2;

    // async load of tile jt into buffer buf
    auto load_tile = [&](int jt, int buf) {
        int j0 = jt * 64;
        __half* Ps = PsA[buf];
        __half* Vs = VsA[buf];
#pragma unroll
        for (int p = 0; p < 4; p++) {
            int idx = p * 256 + tid;        // 1024 = 128 rows x 8 chunks
            int r = idx >> 3, c8 = idx & 7;
            cp16(sm_addr(&Ps[r * 72 + c8 * 8]), &Pb[((size_t)(i0 + r)) * NN + j0 + c8 * 8]);
        }
#pragma unroll
        for (int p = 0; p < 2; p++) {
            int idx = p * 256 + tid;        // 512 = 64 rows x 8 chunks
            int r = idx >> 3, c8 = idx & 7;
            cp16(sm_addr(&Vs[r * 72 + c8 * 8]), &vb[((size_t)(j0 + r)) * DD + c8 * 8]);
        }
        cp_commit();
    };

    load_tile(0, 0);
    for (int jt = 0; jt < njt; jt++) {
        int cur = jt & 1;
        if (jt + 1 < njt) {
            load_tile(jt + 1, 1 - cur);
            asm volatile("cp.async.wait_group 1;\n");
        } else {
            asm volatile("cp.async.wait_group 0;\n");
        }
        __syncthreads();

        unsigned pbase = sm_addr(PsA[cur]), vbase = sm_addr(VsA[cur]);
#pragma unroll
        for (int kk = 0; kk < 64; kk += 16) {
            unsigned a[4][4], b[2][2];
#pragma unroll
            for (int mi = 0; mi < 4; mi++)
                ldsm_x4(a[mi], pbase + ((wm0 + mi * 16 + (l & 15)) * 72 + kk + (l >> 4) * 8) * 2);
#pragma unroll
            for (int ni = 0; ni < 2; ni++)
                ldsm_x2t(b[ni], vbase + ((kk + (l & 15)) * 72 + wn0 + ni * 8) * 2);
#pragma unroll
            for (int mi = 0; mi < 4; mi++)
#pragma unroll
                for (int ni = 0; ni < 2; ni++)
                    mma16816(acc[mi][ni], a[mi], b[ni]);
        }
        __syncthreads();   // buffer 'cur' free before it is refilled at jt+2
    }

    int grp = l >> 2, qd = l & 3;
#pragma unroll
    for (int mi = 0; mi < 4; mi++)
#pragma unroll
        for (int h = 0; h < 2; h++) {
            int row = wm0 + mi * 16 + grp + h * 8;
#pragma unroll
            for (int ni = 0; ni < 2; ni++) {
                int col = wn0 + ni * 8 + qd * 2;
                float2 o = make_float2(acc[mi][ni][2 * h], acc[mi][ni][2 * h + 1]);
                *(float2*)&out[((size_t)bh * NN + i0 + row) * DD + col] = o;
            }
        }
}

// ---------------- launcher ----------------
extern "C" void kernel_launch(void* const* d_in, const int* in_sizes, int n_in,
                              void* d_out, int out_size)
{
    const float* q     = (const float*)d_in[0];
    const float* k     = (const float*)d_in[1];
    const float* v     = (const float*)d_in[2];
    const float* Wpre  = (const float*)d_in[3];
    const float* Wpost = (const float*)d_in[4];
    float* out = (float*)d_out;

    cudaFuncSetAttribute(k_mixp, cudaFuncAttributeMaxDynamicSharedMemorySize, 70 * 1024);
    cudaFuncSetAttribute(k_pv,   cudaFuncAttributeMaxDynamicSharedMemorySize, 56 * 1024);

    // 1) fused prep: head-mix q,k + v->fp16 + q-norms + k-max
    k_prep<<<dim3(NN / 16, BB), 256>>>(q, k, v, Wpre);

    // 1b) zero strictly-upper 32-tiles inside diagonal 128-blocks of g_P
    k_zerop<<<BH * 16, 256>>>();

    // 2) scores via tensor cores + fused exp(s-c) + partial row sums
    k_qk<<<dim3(136, BH), 256>>>();

    // 2b) reduce partial row sums
    k_rsum<<<(BH * NN) / 256, 256>>>();

    // 3) normalize + head-mix probs via tensor cores -> g_P fp16
    k_mixp<<<dim3(2080, BB), 256, 70 * 1024>>>(Wpost);

    // 4) PV via tensor cores, j-tile 64, double-buffered cp.async
    k_pv<<<BH * 16, 256, 56 * 1024>>>(out);
}

// round 14
// speedup vs baseline: 3.4703x; 1.0050x over previous
#include <cuda_runtime.h>
#include <cuda_fp16.h>
#include <math.h>

#define BB 2
#define HH 16
#define NN 2048
#define DD 64
#define BH (BB*HH)
#define SCALE 0.03125f   // 1/(sqrt(16)*sqrt(64))

// ---------------- scratch (static device globals; no allocation) ----------------
__device__ __half g_qh[(size_t)BH*NN*DD];      // head-mixed q, fp16 [b,e,n,d]
__device__ __half g_kh[(size_t)BH*NN*DD];      // head-mixed k, fp16 [b,e,n,d]
__device__ __half g_vh[(size_t)BH*NN*DD];      // v, fp16 [b,h,n,d]
__device__ __half g_S [(size_t)BH*NN*NN];      // unnormalized exp(s - c), fp16 (256MB)
__device__ float  g_rsum[(size_t)BH*NN];       // softmax row sums
__device__ float  g_psum[(size_t)BH*NN*16];    // per-(row, j-tile) partial sums
__device__ float  g_qnorm[(size_t)BH*NN];      // ||q_mixed_i|| (of fp16 values)
__device__ float  g_kmax[BH];                  // max_j ||k_mixed_j|| per (b,h)
// g_kmax: zero-initialized at load; atomicMax over identical deterministic
// inputs is idempotent -> no per-launch reset needed (graph-capture safe).

// ---------------- helpers ----------------
__device__ __forceinline__ unsigned h2u(float a, float b) {
    __half2 h = __floats2half2_rn(a, b);
    return *(unsigned*)&h;
}
__device__ __forceinline__ float4 u2f4(uint2 u) {
    float2 f0 = __half22float2(*(__half2*)&u.x);
    float2 f1 = __half22float2(*(__half2*)&u.y);
    return make_float4(f0.x, f0.y, f1.x, f1.y);
}
__device__ __forceinline__ unsigned sm_addr(const void* p) {
    return (unsigned)__cvta_generic_to_shared(p);
}
__device__ __forceinline__ void ldsm_x4(unsigned* r, unsigned a) {
    asm volatile("ldmatrix.sync.aligned.m8n8.x4.shared.b16 {%0,%1,%2,%3}, [%4];\n"
        : "=r"(r[0]), "=r"(r[1]), "=r"(r[2]), "=r"(r[3]) : "r"(a));
}
__device__ __forceinline__ void ldsm_x2(unsigned* r, unsigned a) {
    asm volatile("ldmatrix.sync.aligned.m8n8.x2.shared.b16 {%0,%1}, [%2];\n"
        : "=r"(r[0]), "=r"(r[1]) : "r"(a));
}
__device__ __forceinline__ void ldsm_x2t(unsigned* r, unsigned a) {
    asm volatile("ldmatrix.sync.aligned.m8n8.x2.trans.shared.b16 {%0,%1}, [%2];\n"
        : "=r"(r[0]), "=r"(r[1]) : "r"(a));
}
__device__ __forceinline__ void mma16816(float* c, const unsigned* a, const unsigned* b) {
    asm volatile(
        "mma.sync.aligned.m16n8k16.row.col.f32.f16.f16.f32 "
        "{%0,%1,%2,%3}, {%4,%5,%6,%7}, {%8,%9}, {%0,%1,%2,%3};\n"
        : "+f"(c[0]), "+f"(c[1]), "+f"(c[2]), "+f"(c[3])
        : "r"(a[0]), "r"(a[1]), "r"(a[2]), "r"(a[3]), "r"(b[0]), "r"(b[1]));
}
__device__ __forceinline__ void cp16(unsigned s, const void* g) {
    asm volatile("cp.async.cg.shared.global [%0], [%1], 16;\n" :: "r"(s), "l"(g));
}
__device__ __forceinline__ void cp_commit() {
    asm volatile("cp.async.commit_group;\n");
}

// ---- K1: fused prep: head-mix q,k (fp16 out) + v->fp16 + q-norms + k-max ----
// block = 256 threads = 16 rows x 16 d-quads; grid = (NN/16, BB)
__global__ void __launch_bounds__(256) k_prep(const float* __restrict__ q,
                                              const float* __restrict__ k,
                                              const float* __restrict__ v,
                                              const float* __restrict__ Wpre)
{
    __shared__ float Ws[HH][HH];
    __shared__ float snorm[HH][16];

    int tid = threadIdx.x;
    Ws[tid >> 4][tid & 15] = Wpre[tid];
    __syncthreads();

    int b  = blockIdx.y;
    int n0 = blockIdx.x * 16;
    int r  = tid >> 4;               // row 0..15
    int dq = tid & 15;               // d-quad 0..15
    int n  = n0 + r;
    size_t base = ((size_t)b * HH * NN + n) * DD + dq * 4;   // + f*NN*DD per head
    const size_t hs = (size_t)NN * DD;

    float acc4[HH][4];
    float sq[HH];

    // ----- q: mix, store fp16, norm of fp16 values -----
#pragma unroll
    for (int e = 0; e < HH; e++) { acc4[e][0] = acc4[e][1] = acc4[e][2] = acc4[e][3] = 0.f; }
#pragma unroll
    for (int f = 0; f < HH; f++) {
        float4 x = *(const float4*)&q[base + f * hs];
#pragma unroll
        for (int e = 0; e < HH; e++) {
            float w = Ws[e][f];
            acc4[e][0] += w * x.x; acc4[e][1] += w * x.y;
            acc4[e][2] += w * x.z; acc4[e][3] += w * x.w;
        }
    }
#pragma unroll
    for (int e = 0; e < HH; e++) {
        uint2 hv = make_uint2(h2u(acc4[e][0], acc4[e][1]), h2u(acc4[e][2], acc4[e][3]));
        *(uint2*)&g_qh[base + e * hs] = hv;
        float4 fb = u2f4(hv);                       // fp16-rounded values
        sq[e] = fb.x * fb.x + fb.y * fb.y + fb.z * fb.z + fb.w * fb.w;
    }
#pragma unroll
    for (int e = 0; e < HH; e++) {
        float s = sq[e];
        s += __shfl_xor_sync(0xffffffff, s, 1);
        s += __shfl_xor_sync(0xffffffff, s, 2);
        s += __shfl_xor_sync(0xffffffff, s, 4);
        s += __shfl_xor_sync(0xffffffff, s, 8);
        if (dq == 0) snorm[e][r] = s;
    }
    __syncthreads();
    g_qnorm[(size_t)(b * HH + (tid >> 4)) * NN + n0 + (tid & 15)] =
        sqrtf(snorm[tid >> 4][tid & 15]);
    __syncthreads();                                 // before snorm reuse

    // ----- k: mix, store fp16, per-head max norm -----
#pragma unroll
    for (int e = 0; e < HH; e++) { acc4[e][0] = acc4[e][1] = acc4[e][2] = acc4[e][3] = 0.f; }
#pragma unroll
    for (int f = 0; f < HH; f++) {
        float4 x = *(const float4*)&k[base + f * hs];
#pragma unroll
        for (int e = 0; e < HH; e++) {
            float w = Ws[e][f];
            acc4[e][0] += w * x.x; acc4[e][1] += w * x.y;
            acc4[e][2] += w * x.z; acc4[e][3] += w * x.w;
        }
    }
#pragma unroll
    for (int e = 0; e < HH; e++) {
        uint2 hv = make_uint2(h2u(acc4[e][0], acc4[e][1]), h2u(acc4[e][2], acc4[e][3]));
        *(uint2*)&g_kh[base + e * hs] = hv;
        float4 fb = u2f4(hv);
        sq[e] = fb.x * fb.x + fb.y * fb.y + fb.z * fb.z + fb.w * fb.w;
    }
#pragma unroll
    for (int e = 0; e < HH; e++) {
        float s = sq[e];
        s += __shfl_xor_sync(0xffffffff, s, 1);
        s += __shfl_xor_sync(0xffffffff, s, 2);
        s += __shfl_xor_sync(0xffffffff, s, 4);
        s += __shfl_xor_sync(0xffffffff, s, 8);
        if (dq == 0) snorm[e][r] = s;
    }
    __syncthreads();
    {
        float s2 = snorm[tid >> 4][tid & 15];        // (e = tid>>4, row = tid&15)
        s2 = fmaxf(s2, __shfl_xor_sync(0xffffffff, s2, 1));
        s2 = fmaxf(s2, __shfl_xor_sync(0xffffffff, s2, 2));
        s2 = fmaxf(s2, __shfl_xor_sync(0xffffffff, s2, 4));
        s2 = fmaxf(s2, __shfl_xor_sync(0xffffffff, s2, 8));
        if ((tid & 15) == 0)
            atomicMax((int*)&g_kmax[b * HH + (tid >> 4)], __float_as_int(sqrtf(s2)));
    }

    // ----- v -> fp16 (no mixing) -----
#pragma unroll
    for (int f = 0; f < HH; f++) {
        float4 x = *(const float4*)&v[base + f * hs];
        *(uint2*)&g_vh[base + f * hs] = make_uint2(h2u(x.x, x.y), h2u(x.z, x.w));
    }
}

// ---- K2: lower-tri 128x128x64 tensor-core GEMM + fused exp(s-c) + partial sums,
//      coalesced S store via smem staging (reuses Q/K smem) ----
__global__ void __launch_bounds__(256) k_qk()
{
    __shared__ __half QK[2 * 128 * 72];        // Qs | Ks, reused as St staging
    __shared__ float  psumS[128][4];
    __half* Qs = QK;
    __half* Ks = QK + 128 * 72;
    __half* St = QK;                           // 128 x 136 staging

    int pidx = blockIdx.x;       // 0..135 lower-tri pair (ti>=tj)
    int ti = (int)((sqrtf(8.f * pidx + 1.f) - 1.f) * 0.5f);
    while ((ti + 1) * (ti + 2) / 2 <= pidx) ti++;
    while (ti * (ti + 1) / 2 > pidx) ti--;
    int tj = pidx - ti * (ti + 1) / 2;
    int bh = blockIdx.y;

    const __half* qb = g_qh + ((size_t)bh * NN + ti * 128) * DD;
    const __half* kb = g_kh + ((size_t)bh * NN + tj * 128) * DD;

    int tid = threadIdx.x;
#pragma unroll
    for (int p = 0; p < 4; p++) {
        int idx = p * 256 + tid;            // 1024 = 128 rows x 8 chunks
        int r = idx >> 3, c8 = idx & 7;
        *(uint4*)&Qs[r * 72 + c8 * 8] = *(const uint4*)&qb[r * 64 + c8 * 8];
        *(uint4*)&Ks[r * 72 + c8 * 8] = *(const uint4*)&kb[r * 64 + c8 * 8];
    }
    __syncthreads();

    int w = tid >> 5, l = tid & 31;
    int wm0 = (w >> 2) * 64;                // warp rows
    int wn0 = (w & 3) * 32;                 // warp cols
    unsigned qbase = sm_addr(Qs), kbase = sm_addr(Ks);

    float acc[4][4][4];
#pragma unroll
    for (int mi = 0; mi < 4; mi++)
#pragma unroll
        for (int ni = 0; ni < 4; ni++)
#pragma unroll
            for (int u = 0; u < 4; u++) acc[mi][ni][u] = 0.f;

#pragma unroll
    for (int kk = 0; kk < 64; kk += 16) {
        unsigned a[4][4], b[4][2];
#pragma unroll
        for (int mi = 0; mi < 4; mi++)
            ldsm_x4(a[mi], qbase + ((wm0 + mi * 16 + (l & 15)) * 72 + kk + (l >> 4) * 8) * 2);
#pragma unroll
        for (int ni = 0; ni < 4; ni++)
            ldsm_x2(b[ni], kbase + ((wn0 + ni * 8 + (l & 7)) * 72 + kk + ((l >> 3) & 1) * 8) * 2);
#pragma unroll
        for (int mi = 0; mi < 4; mi++)
#pragma unroll
            for (int ni = 0; ni < 4; ni++)
                mma16816(acc[mi][ni], a[mi], b[ni]);
    }
    __syncthreads();               // Qs/Ks dead -> safe to reuse as St

    float kmaxv = g_kmax[bh];
    bool isdiag = (ti == tj);
    int grp = l >> 2, qd = l & 3;

#pragma unroll
    for (int mi = 0; mi < 4; mi++) {
#pragma unroll
        for (int h = 0; h < 2; h++) {
            int row = wm0 + mi * 16 + grp + h * 8;
            float cb = SCALE * g_qnorm[(size_t)bh * NN + ti * 128 + row] * kmaxv;
            float rsum = 0.f;
#pragma unroll
            for (int ni = 0; ni < 4; ni++) {
                int col = wn0 + ni * 8 + qd * 2;
                float e0 = __expf(acc[mi][ni][2 * h]     * SCALE - cb);
                float e1 = __expf(acc[mi][ni][2 * h + 1] * SCALE - cb);
                if (isdiag && col     > row) e0 = 0.f;
                if (isdiag && col + 1 > row) e1 = 0.f;
                rsum += e0 + e1;
                *(unsigned*)&St[row * 136 + col] = h2u(e0, e1);
            }
            rsum += __shfl_xor_sync(0xffffffff, rsum, 1);
            rsum += __shfl_xor_sync(0xffffffff, rsum, 2);
            if (qd == 0) psumS[row][w & 3] = rsum;
        }
    }
    __syncthreads();

    __half* Sb = g_S + (size_t)bh * NN * NN;
#pragma unroll
    for (int p = 0; p < 8; p++) {
        int idx = p * 256 + tid;           // 2048 = 128 rows x 16 chunks
        int r = idx >> 4, c8 = idx & 15;
        *(uint4*)&Sb[(size_t)(ti * 128 + r) * NN + tj * 128 + c8 * 8] =
            *(uint4*)&St[r * 136 + c8 * 8];
    }
    if (tid < 128) {
        float s = psumS[tid][0] + psumS[tid][1] + psumS[tid][2] + psumS[tid][3];
        g_psum[((size_t)bh * NN + ti * 128 + tid) * 16 + tj] = s;
    }
}

// ---------------- K3: reduce partial row sums ----------------
__global__ void k_rsum()
{
    size_t idx = (size_t)blockIdx.x * 256 + threadIdx.x;   // BH*NN rows
    int i = (int)(idx & (NN - 1));
    int nt = (i >> 7) + 1;
    const float* p = g_psum + idx * 16;
    float s = 0.f;
    for (int t = 0; t < nt; t++) s += p[t];
    g_rsum[idx] = s;
}

// ---- K4 (fused): normalize + head-mix + PV, no P intermediate ----
// CTA = (b, 32-row i-band t, e-half). Warp w owns e = eh*8+w.
// Loops j-tiles of 32 with cp.async double buffering of S (16 f-heads) and V (8 e-heads).
// S is already causally masked (k_qk zeroes j>i in the diagonal 128-block), so
// mixed P is automatically zero above the diagonal -> no masking here.
__global__ void __launch_bounds__(256) k_mixpv(const float* __restrict__ Wpost,
                                               float* __restrict__ out)
{
    extern __shared__ char smb[];
    float*  invl = (float*)(smb);                         // 16x32 fp32      (2048B)
    __half* Wh   = (__half*)(smb + 2048);                 // 16x24 halves    (pad 1024B)
    __half* BsA[2] = { (__half*)(smb + 3072),             // 16f x 1032 halves (33024B)
                       (__half*)(smb + 36096) };          // 33024B
    __half* VsA[2] = { (__half*)(smb + 69120),            // 8e x 32 x 72 halves (36864B)
                       (__half*)(smb + 105984) };         // 36864B
    __half* Ps   = (__half*)(smb + 142848);               // 8e x 1288 halves (20608B)
    // total 163456B

    int bi = blockIdx.x;
    int eh = bi & 1;                       // twin CTAs adjacent -> S L2 reuse
    int t  = 63 - ((bi >> 1) & 63);        // heavy i-bands first
    int b  = bi >> 7;
    int i0 = t * 32;

    int tid = threadIdx.x;
    int w = tid >> 5, l = tid & 31;
    int grp = l >> 2, qd = l & 3;

    // W rows 0..7 = this half's e rows; rows 8..15 zero (ignore c2/c3 of mix mma)
    {
        int r = tid >> 4, f = tid & 15;
        float wv = (r < 8) ? Wpost[(eh * 8 + r) * HH + f] : 0.f;
        Wh[r * 24 + f] = __float2half_rn(wv);
    }
#pragma unroll
    for (int q2 = 0; q2 < 2; q2++) {
        int idx = q2 * 256 + tid;          // 512 = 16f x 32i
        int f = idx >> 5, r = idx & 31;
        invl[f * 32 + r] = 1.0f / g_rsum[(size_t)(b * HH + f) * NN + i0 + r];
    }
    __syncthreads();

    unsigned wfrag[4];
    ldsm_x4(wfrag, sm_addr(Wh) + ((l & 15) * 24 + (l >> 4) * 8) * 2);

    float acc[2][8][4];
#pragma unroll
    for (int mi = 0; mi < 2; mi++)
#pragma unroll
        for (int ni = 0; ni < 8; ni++)
#pragma unroll
            for (int u = 0; u < 4; u++) acc[mi][ni][u] = 0.f;

    auto prefetch = [&](int jt, int buf) {
        int j0 = jt * 32;
        __half* Bs = BsA[buf];
        __half* Vs = VsA[buf];
#pragma unroll
        for (int p = 0; p < 8; p++) {      // S: 16f x 32r x 4 chunks
            int idx = p * 256 + tid;
            int f = idx >> 7, r = (idx >> 2) & 31, c = idx & 3;
            cp16(sm_addr(&Bs[f * 1032 + r * 32 + c * 8]),
                 &g_S[((size_t)(b * HH + f) * NN + i0 + r) * NN + j0 + c * 8]);
        }
#pragma unroll
        for (int p = 0; p < 8; p++) {      // V: 8e x 32r x 8 chunks
            int idx = p * 256 + tid;
            int e = idx >> 8, r = (idx >> 3) & 31, c8 = idx & 7;
            cp16(sm_addr(&Vs[e * 2304 + r * 72 + c8 * 8]),
                 &g_vh[((size_t)(b * HH + eh * 8 + e) * NN + j0 + r) * DD + c8 * 8]);
        }
        cp_commit();
    };

    int njt = t + 1;
    prefetch(0, 0);
    for (int jt = 0; jt < njt; jt++) {
        int cur = jt & 1;
        if (jt + 1 < njt) {
            prefetch(jt + 1, 1 - cur);
            asm volatile("cp.async.wait_group 1;\n");
        } else {
            asm volatile("cp.async.wait_group 0;\n");
        }
        __syncthreads();

        // normalize in place: Sn = S * invl[f][i]
        {
            __half* Bs = BsA[cur];
#pragma unroll
            for (int q2 = 0; q2 < 16; q2++) {
                int idx = q2 * 256 + tid;  // 4096 uint2
                int f = idx >> 8, i = (idx >> 3) & 31, c4 = idx & 7;
                __half* p = &Bs[f * 1032 + i * 32 + c4 * 4];
                uint2 uv = *(uint2*)p;
                float4 v4 = u2f4(uv);
                float il = invl[f * 32 + i];
                *(uint2*)p = make_uint2(h2u(v4.x * il, v4.y * il),
                                        h2u(v4.z * il, v4.w * il));
            }
        }
        __syncthreads();

        // mix: Ps[e(8), i(32), j(32)] = W(8x16) @ Sn(16f x 1024 sites)
        {
            unsigned bbase = sm_addr(BsA[cur]);
#pragma unroll
            for (int tt = 0; tt < 16; tt++) {
                int s0 = (w * 16 + tt) * 8;
                unsigned bfr[2];
                ldsm_x2t(bfr, bbase + ((l & 15) * 1032 + s0) * 2);
                float c[4] = {0.f, 0.f, 0.f, 0.f};
                mma16816(c, wfrag, bfr);
                int s = s0 + qd * 2;
                int ii = s >> 5, jj = s & 31;
                *(unsigned*)&Ps[grp * 1288 + ii * 40 + jj] = h2u(c[0], c[1]);
            }
        }
        __syncthreads();

        // PV: acc[e=w] += P_e(32i x 32j) @ V_e(32j x 64d)
        {
            unsigned pbase = sm_addr(Ps) + w * 1288 * 2;
            unsigned vbase = sm_addr(VsA[cur]) + w * 2304 * 2;
#pragma unroll
            for (int kk = 0; kk < 32; kk += 16) {
                unsigned a[2][4], bfr[8][2];
#pragma unroll
                for (int mi = 0; mi < 2; mi++)
                    ldsm_x4(a[mi], pbase + ((mi * 16 + (l & 15)) * 40 + kk + (l >> 4) * 8) * 2);
#pragma unroll
                for (int ni = 0; ni < 8; ni++)
                    ldsm_x2t(bfr[ni], vbase + ((kk + (l & 15)) * 72 + ni * 8) * 2);
#pragma unroll
                for (int mi = 0; mi < 2; mi++)
#pragma unroll
                    for (int ni = 0; ni < 8; ni++)
                        mma16816(acc[mi][ni], a[mi], bfr[ni]);
            }
        }
        __syncthreads();   // Ps/Bs/Vs[cur] free before reuse
    }

    // epilogue: out[b, eh*8+w, i0+row, col]
#pragma unroll
    for (int mi = 0; mi < 2; mi++)
#pragma unroll
        for (int h = 0; h < 2; h++) {
            int row = mi * 16 + grp + h * 8;
#pragma unroll
            for (int ni = 0; ni < 8; ni++) {
                int col = ni * 8 + qd * 2;
                float2 o = make_float2(acc[mi][ni][2 * h], acc[mi][ni][2 * h + 1]);
                *(float2*)&out[((size_t)(b * HH + eh * 8 + w) * NN + i0 + row) * DD + col] = o;
            }
        }
}

// ---------------- launcher ----------------
extern "C" void kernel_launch(void* const* d_in, const int* in_sizes, int n_in,
                              void* d_out, int out_size)
{
    const float* q     = (const float*)d_in[0];
    const float* k     = (const float*)d_in[1];
    const float* v     = (const float*)d_in[2];
    const float* Wpre  = (const float*)d_in[3];
    const float* Wpost = (const float*)d_in[4];
    float* out = (float*)d_out;

    cudaFuncSetAttribute(k_mixpv, cudaFuncAttributeMaxDynamicSharedMemorySize, 163456);

    // 1) fused prep: head-mix q,k + v->fp16 + q-norms + k-max
    k_prep<<<dim3(NN / 16, BB), 256>>>(q, k, v, Wpre);

    // 2) scores via tensor cores + fused exp(s-c) + partial row sums
    k_qk<<<dim3(136, BH), 256>>>();

    // 2b) reduce partial row sums
    k_rsum<<<(BH * NN) / 256, 256>>>();

    // 3) fused normalize + head-mix + PV (no P intermediate)
    k_mixpv<<<256, 256, 163456>>>(Wpost, out);
}